// round 2
// baseline (speedup 1.0000x reference)
#include <cuda_runtime.h>

#define NFR 8
#define NO 197
#define NB 8
#define NTOK 1576          // 8*197
#define CDIM 768
#define NH 12
#define HD 64
#define MG 204             // gathered tokens
#define ROWS_X 12608       // 8*1576 == 64*197
#define ROWS_KV 1632       // 8*204

// Scratch (no allocations allowed -> device globals)
__device__ float g_Q[ROWS_X * CDIM];          // Q projection, scaled by 1/8
__device__ float g_KV[ROWS_KV * 2 * CDIM];    // per gathered row: [K(768) | V(768)]
__device__ float g_AO[ROWS_X * CDIM];         // attention output
__device__ int   g_idx[MG];

// ---------------------------------------------------------------------------
// Build gather indices (static function of NO/NFR; recomputed each launch,
// deterministic).
// cls: idx[m] = m*197 for m<8.
// frame f element j: idx = f*197 + 1 + f + 8*j ; frames 0..3 have 25 elems,
// frames 4..7 have 24.
// ---------------------------------------------------------------------------
__global__ void init_idx_kernel() {
    int m = threadIdx.x;
    if (m >= MG) return;
    if (m < NFR) { g_idx[m] = m * NO; return; }
    int mm = m - NFR;
    int f, j;
    if (mm < 100) { f = mm / 25; j = mm - f * 25; }
    else          { f = 4 + (mm - 100) / 24; j = (mm - 100) - (f - 4) * 24; }
    g_idx[m] = f * NO + 1 + f + 8 * j;
}

// ---------------------------------------------------------------------------
// C[M,N] = alpha * A[M,K] @ W[N,K]^T + bias   (both operands K-contiguous)
// 128x128 tile, BK=8, 256 threads, 8x8 per-thread microkernel.
// gather!=0: logical row r -> physical A row (r/204)*1576 + g_idx[r%204]
// N must be a multiple of 128; M is guarded.
// ---------------------------------------------------------------------------
__global__ __launch_bounds__(256) void gemm_nt_kernel(
    const float* __restrict__ A, const float* __restrict__ W,
    float* __restrict__ Co, int M, int N, int K,
    const float* __restrict__ bias, float alpha, int gather)
{
    __shared__ float As[8][128];
    __shared__ float Bs[8][128];

    const int tid = threadIdx.x;
    const int bm = blockIdx.y * 128;
    const int bn = blockIdx.x * 128;

    const int lrow = tid >> 1;          // 0..127
    const int lk   = (tid & 1) * 4;     // 0 or 4

    int ar = bm + lrow;
    const bool a_ok = ar < M;
    long arow = a_ok ? ar : 0;
    if (gather) {
        int bb = (int)(arow / MG);
        int mm = (int)(arow - (long)bb * MG);
        arow = (long)bb * NTOK + g_idx[mm];
    }
    const float* Ap = A + arow * (long)K;
    const float* Bp = W + (long)(bn + lrow) * K;

    float acc[8][8];
#pragma unroll
    for (int i = 0; i < 8; i++)
#pragma unroll
        for (int j = 0; j < 8; j++) acc[i][j] = 0.f;

    const int tr = (tid >> 4) * 8;
    const int tc = (tid & 15) * 8;

    for (int k0 = 0; k0 < K; k0 += 8) {
        float4 a4 = a_ok ? *(const float4*)(Ap + k0 + lk) : make_float4(0.f, 0.f, 0.f, 0.f);
        float4 b4 = *(const float4*)(Bp + k0 + lk);
        As[lk + 0][lrow] = a4.x; As[lk + 1][lrow] = a4.y;
        As[lk + 2][lrow] = a4.z; As[lk + 3][lrow] = a4.w;
        Bs[lk + 0][lrow] = b4.x; Bs[lk + 1][lrow] = b4.y;
        Bs[lk + 2][lrow] = b4.z; Bs[lk + 3][lrow] = b4.w;
        __syncthreads();
#pragma unroll
        for (int kk = 0; kk < 8; kk++) {
            float ra[8], rb[8];
            *(float4*)(ra)     = *(const float4*)&As[kk][tr];
            *(float4*)(ra + 4) = *(const float4*)&As[kk][tr + 4];
            *(float4*)(rb)     = *(const float4*)&Bs[kk][tc];
            *(float4*)(rb + 4) = *(const float4*)&Bs[kk][tc + 4];
#pragma unroll
            for (int i = 0; i < 8; i++)
#pragma unroll
                for (int j = 0; j < 8; j++)
                    acc[i][j] += ra[i] * rb[j];
        }
        __syncthreads();
    }

    float bv[8];
#pragma unroll
    for (int j = 0; j < 8; j++) bv[j] = bias ? bias[bn + tc + j] : 0.f;

#pragma unroll
    for (int i = 0; i < 8; i++) {
        int r = bm + tr + i;
        if (r >= M) continue;
        float* cp = Co + (long)r * N + bn + tc;
        float4 v0, v1;
        v0.x = acc[i][0] * alpha + bv[0]; v0.y = acc[i][1] * alpha + bv[1];
        v0.z = acc[i][2] * alpha + bv[2]; v0.w = acc[i][3] * alpha + bv[3];
        v1.x = acc[i][4] * alpha + bv[4]; v1.y = acc[i][5] * alpha + bv[5];
        v1.z = acc[i][6] * alpha + bv[6]; v1.w = acc[i][7] * alpha + bv[7];
        ((float4*)cp)[0] = v0;
        ((float4*)cp)[1] = v1;
    }
}

// ---------------------------------------------------------------------------
// Fused attention per (b, h, 64-row query tile).
// K,V,Q tiles in smem (stride 68 floats to kill bank conflicts).
// Thread (row = tid/4, sub = tid%4) owns 51 columns of the 204-wide score row.
// Mask 1.0/0.8 computed analytically. Softmax across the 4-thread group via
// shfl_xor. Scores already include the 1/8 scale (folded into Q GEMM).
// ---------------------------------------------------------------------------
#define LDK 68
#define ATTN_SMEM_FLOATS ((64 + MG + MG) * LDK)

__global__ __launch_bounds__(256) void attn_kernel() {
    extern __shared__ float smem[];
    float* Qs = smem;                 // 64  x 68
    float* Ks = smem + 64 * LDK;      // 204 x 68
    float* Vs = Ks + MG * LDK;        // 204 x 68

    const int b = blockIdx.z, h = blockIdx.y;
    const int n0 = blockIdx.x * 64;
    const int tid = threadIdx.x;

    // Load K and V tiles (204 x 64 each)
    for (int i = tid; i < MG * 16; i += 256) {
        int m = i >> 4, q = i & 15;
        const float* base = g_KV + (size_t)(b * MG + m) * (2 * CDIM) + h * HD;
        ((float4*)(Ks + m * LDK))[q] = ((const float4*)base)[q];
        ((float4*)(Vs + m * LDK))[q] = ((const float4*)(base + CDIM))[q];
    }
    // Load Q tile (64 x 64), zero-padded past N
    for (int i = tid; i < 64 * 16; i += 256) {
        int r = i >> 4, q = i & 15;
        int n = n0 + r;
        float4 v = make_float4(0.f, 0.f, 0.f, 0.f);
        if (n < NTOK)
            v = ((const float4*)(g_Q + (size_t)(b * NTOK + n) * CDIM + h * HD))[q];
        ((float4*)(Qs + r * LDK))[q] = v;
    }
    __syncthreads();

    const int row = tid >> 2;
    const int sub = tid & 3;
    const int n = n0 + row;
    const bool valid = n < NTOK;
    const int nf = valid ? n / NO : 0;

    float s[51];
#pragma unroll
    for (int jj = 0; jj < 51; jj++) s[jj] = 0.f;

    const float* qrow = Qs + row * LDK;
    const float* kb = Ks + (sub * 51) * LDK;
    for (int d0 = 0; d0 < 64; d0 += 4) {
        float4 q4 = *(const float4*)(qrow + d0);
#pragma unroll
        for (int jj = 0; jj < 51; jj++) {
            float4 k4 = *(const float4*)(kb + jj * LDK + d0);
            s[jj] += q4.x * k4.x + q4.y * k4.y + q4.z * k4.z + q4.w * k4.w;
        }
    }

    // multiplicative mask on scaled scores
#pragma unroll
    for (int jj = 0; jj < 51; jj++) {
        int m = sub * 51 + jj;
        float mk;
        if (m < NFR) mk = 1.f;
        else {
            int mm = m - NFR;
            int f = (mm < 100) ? (mm / 25) : (4 + (mm - 100) / 24);
            mk = (f == nf) ? 1.f : 0.8f;
        }
        s[jj] *= mk;
    }

    // softmax over 204 cols spread across 4 threads
    float mx = -1e30f;
#pragma unroll
    for (int jj = 0; jj < 51; jj++) mx = fmaxf(mx, s[jj]);
    mx = fmaxf(mx, __shfl_xor_sync(0xffffffffu, mx, 1));
    mx = fmaxf(mx, __shfl_xor_sync(0xffffffffu, mx, 2));
    float sum = 0.f;
#pragma unroll
    for (int jj = 0; jj < 51; jj++) { s[jj] = __expf(s[jj] - mx); sum += s[jj]; }
    sum += __shfl_xor_sync(0xffffffffu, sum, 1);
    sum += __shfl_xor_sync(0xffffffffu, sum, 2);
    float inv = 1.f / sum;
#pragma unroll
    for (int jj = 0; jj < 51; jj++) s[jj] *= inv;

    // P @ V in 16-wide d-chunks; reduce partials across the 4-thread group
    const float* vb = Vs + (sub * 51) * LDK;
    float* outp = g_AO + (size_t)(b * NTOK + n) * CDIM + h * HD;
    for (int dc = 0; dc < 64; dc += 16) {
        float o[16];
#pragma unroll
        for (int d = 0; d < 16; d++) o[d] = 0.f;
#pragma unroll
        for (int jj = 0; jj < 51; jj++) {
            float p = s[jj];
#pragma unroll
            for (int u = 0; u < 4; u++) {
                float4 v4 = *(const float4*)(vb + jj * LDK + dc + 4 * u);
                o[4 * u + 0] += p * v4.x;
                o[4 * u + 1] += p * v4.y;
                o[4 * u + 2] += p * v4.z;
                o[4 * u + 3] += p * v4.w;
            }
        }
#pragma unroll
        for (int d = 0; d < 16; d++) {
            o[d] += __shfl_xor_sync(0xffffffffu, o[d], 1);
            o[d] += __shfl_xor_sync(0xffffffffu, o[d], 2);
        }
        if (sub == 0 && valid) {
            ((float4*)(outp + dc))[0] = make_float4(o[0], o[1], o[2], o[3]);
            ((float4*)(outp + dc))[1] = make_float4(o[4], o[5], o[6], o[7]);
            ((float4*)(outp + dc))[2] = make_float4(o[8], o[9], o[10], o[11]);
            ((float4*)(outp + dc))[3] = make_float4(o[12], o[13], o[14], o[15]);
        }
    }
}

// ---------------------------------------------------------------------------
extern "C" void kernel_launch(void* const* d_in, const int* in_sizes, int n_in,
                              void* d_out, int out_size) {
    const float* x      = (const float*)d_in[0];  // (64,197,768) == (12608,768)
    const float* qkv_w  = (const float*)d_in[1];  // (2304,768): Wq|Wk|Wv
    const float* proj_w = (const float*)d_in[2];  // (768,768)
    const float* proj_b = (const float*)d_in[3];  // (768,)
    float* out = (float*)d_out;

    float *pQ, *pKV, *pAO;
    cudaGetSymbolAddress((void**)&pQ, g_Q);
    cudaGetSymbolAddress((void**)&pKV, g_KV);
    cudaGetSymbolAddress((void**)&pAO, g_AO);
    cudaFuncSetAttribute(attn_kernel, cudaFuncAttributeMaxDynamicSharedMemorySize,
                         ATTN_SMEM_FLOATS * 4);

    init_idx_kernel<<<1, 256>>>();

    // Q = X @ Wq^T * (1/sqrt(64))  -> all 12608 rows
    dim3 gq(CDIM / 128, (ROWS_X + 127) / 128);
    gemm_nt_kernel<<<gq, 256>>>(x, qkv_w, pQ, ROWS_X, CDIM, CDIM,
                                nullptr, 0.125f, 0);

    // [K|V] on gathered rows only (8*204 rows x 1536 cols)
    dim3 gkv(1536 / 128, (ROWS_KV + 127) / 128);
    gemm_nt_kernel<<<gkv, 256>>>(x, qkv_w + 768 * 768, pKV, ROWS_KV, 1536, CDIM,
                                 nullptr, 1.f, 1);

    // fused attention
    dim3 ga((NTOK + 63) / 64, NH, NB);
    attn_kernel<<<ga, 256, ATTN_SMEM_FLOATS * 4>>>();

    // out = AO @ proj_w^T + proj_b
    gemm_nt_kernel<<<gq, 256>>>(pAO, proj_w, out, ROWS_X, CDIM, CDIM,
                                proj_b, 1.f, 0);
}

// round 5
// speedup vs baseline: 1.2540x; 1.2540x over previous
#include <cuda_runtime.h>
#include <cuda_bf16.h>
#include <cstdint>

#define NFR 8
#define NO 197
#define NB 8
#define NTOK 1576          // 8*197
#define CDIM 768
#define NH 12
#define HD 64
#define MG 204             // gathered tokens
#define MPAD 208
#define ROWS_X 12608       // 64*197
#define ROWS_KV 1632       // 8*204

// ---------------- scratch (no allocs allowed -> device globals) -------------
__device__ float g_Q[ROWS_X * CDIM];
__device__ float g_KV[ROWS_KV * 2 * CDIM];
__device__ int   g_idx[MG];
__device__ __nv_bfloat16 g_Xhi[ROWS_X * CDIM];
__device__ __nv_bfloat16 g_Xlo[ROWS_X * CDIM];
__device__ __nv_bfloat16 g_Whi[3 * CDIM * CDIM];
__device__ __nv_bfloat16 g_Wlo[3 * CDIM * CDIM];
__device__ __nv_bfloat16 g_Phi[CDIM * CDIM];
__device__ __nv_bfloat16 g_Plo[CDIM * CDIM];
__device__ __nv_bfloat16 g_AOhi[ROWS_X * CDIM];
__device__ __nv_bfloat16 g_AOlo[ROWS_X * CDIM];

// ---------------------------------------------------------------------------
__global__ void init_idx_kernel() {
    int m = threadIdx.x;
    if (m >= MG) return;
    if (m < NFR) { g_idx[m] = m * NO; return; }
    int mm = m - NFR;
    int f, j;
    if (mm < 100) { f = mm / 25; j = mm - f * 25; }
    else          { f = 4 + (mm - 100) / 24; j = (mm - 100) - (f - 4) * 24; }
    g_idx[m] = f * NO + 1 + f + 8 * j;
}

// fp32 -> (bf16 hi, bf16 lo) split
__global__ void cvt_kernel(const float* __restrict__ src,
                           __nv_bfloat16* __restrict__ hi,
                           __nv_bfloat16* __restrict__ lo, int n4) {
    int i = blockIdx.x * blockDim.x + threadIdx.x;
    if (i >= n4) return;
    float4 v = ((const float4*)src)[i];
    float f[4] = {v.x, v.y, v.z, v.w};
    __nv_bfloat16 hh[4], ll[4];
#pragma unroll
    for (int k = 0; k < 4; k++) {
        hh[k] = __float2bfloat16(f[k]);
        ll[k] = __float2bfloat16(f[k] - __bfloat162float(hh[k]));
    }
    __nv_bfloat162 h0, h1, l0, l1;
    h0.x = hh[0]; h0.y = hh[1]; h1.x = hh[2]; h1.y = hh[3];
    l0.x = ll[0]; l0.y = ll[1]; l1.x = ll[2]; l1.y = ll[3];
    ((__nv_bfloat162*)hi)[2 * i]     = h0;
    ((__nv_bfloat162*)hi)[2 * i + 1] = h1;
    ((__nv_bfloat162*)lo)[2 * i]     = l0;
    ((__nv_bfloat162*)lo)[2 * i + 1] = l1;
}

// ---------------------------------------------------------------------------
// mma.sync helpers (base sm_103 PTX -- no tcgen05 available in this harness)
// ---------------------------------------------------------------------------
__device__ __forceinline__ uint32_t smem_u32(const void* p) {
    uint32_t a;
    asm("{ .reg .u64 t; cvta.to.shared.u64 t, %1; cvt.u32.u64 %0, t; }"
        : "=r"(a) : "l"(p));
    return a;
}
#define LDSM_X4(r0, r1, r2, r3, addr)                                        \
    asm volatile("ldmatrix.sync.aligned.m8n8.x4.shared.b16 {%0,%1,%2,%3}, [%4];" \
                 : "=r"(r0), "=r"(r1), "=r"(r2), "=r"(r3) : "r"(addr))
#define MMA16816(d, a, b0, b1)                                               \
    asm volatile("mma.sync.aligned.m16n8k16.row.col.f32.bf16.bf16.f32 "      \
                 "{%0,%1,%2,%3}, {%4,%5,%6,%7}, {%8,%9}, {%0,%1,%2,%3};"     \
                 : "+f"((d)[0]), "+f"((d)[1]), "+f"((d)[2]), "+f"((d)[3])    \
                 : "r"((a)[0]), "r"((a)[1]), "r"((a)[2]), "r"((a)[3]),       \
                   "r"(b0), "r"(b1))

// ---------------------------------------------------------------------------
// C[M,N] = alpha * A[M,768] @ W[N,768]^T + bias, bf16 hi/lo 3-product via
// mma.sync m16n8k16. 128x128 CTA tile, BK=64, 8 warps (32x64 each).
// smem rows padded to 72 bf16 (144B) -> conflict-free ldmatrix.
// gather!=0: logical A row r -> (r/204)*1576 + g_idx[r%204]
// ---------------------------------------------------------------------------
#define LDS_PAD 72
#define ARR_ELEMS (128 * LDS_PAD)
#define GEMM_SMEM (4 * ARR_ELEMS * 2)

__global__ __launch_bounds__(256)
void gemm_mma(const __nv_bfloat16* __restrict__ Ahi, const __nv_bfloat16* __restrict__ Alo,
              const __nv_bfloat16* __restrict__ Bhi, const __nv_bfloat16* __restrict__ Blo,
              float* __restrict__ C, int M, int N,
              const float* __restrict__ bias, float alpha, int gather)
{
    extern __shared__ __nv_bfloat16 smem[];
    __nv_bfloat16* const sArr[4] = { smem, smem + ARR_ELEMS,
                                     smem + 2 * ARR_ELEMS, smem + 3 * ARR_ELEMS };
    const int tid = threadIdx.x;
    const int wid = tid >> 5, lane = tid & 31;
    const int bm = blockIdx.y * 128, bn = blockIdx.x * 128;
    const int warp_m = wid & 3, warp_n = wid >> 2;

    const uint32_t sbase = smem_u32(smem);
    const uint32_t sA_hi = sbase;
    const uint32_t sA_lo = sbase + ARR_ELEMS * 2;
    const uint32_t sB_hi = sbase + 2 * ARR_ELEMS * 2;
    const uint32_t sB_lo = sbase + 3 * ARR_ELEMS * 2;

    float acc[2][8][4];
#pragma unroll
    for (int mt = 0; mt < 2; mt++)
#pragma unroll
        for (int nt = 0; nt < 8; nt++)
#pragma unroll
            for (int e = 0; e < 4; e++) acc[mt][nt][e] = 0.f;

    // ldmatrix lane address components
    const int a_row  = lane & 15;
    const int a_koff = (lane >> 4) << 3;
    const int b_row  = ((lane >> 4) << 3) + (lane & 7);
    const int b_koff = ((lane >> 3) & 1) << 3;

    for (int c = 0; c < 12; c++) {
        const int k0 = c * 64;
        // ---- stage 128x64 of Ahi/Alo/Bhi/Blo into smem ----
#pragma unroll 4
        for (int i = tid; i < 4096; i += 256) {
            int a = i >> 10;             // 0:Ahi 1:Alo 2:Bhi 3:Blo
            int row = (i >> 3) & 127;
            int slot = i & 7;
            const __nv_bfloat16* src;
            int r;
            if (a < 2) {
                r = bm + row; if (r >= M) r = 0;
                if (gather) { int bb = r / MG; int mm = r - bb * MG; r = bb * NTOK + g_idx[mm]; }
                src = (a == 0) ? Ahi : Alo;
            } else {
                r = bn + row;
                src = (a == 2) ? Bhi : Blo;
            }
            uint4 v = *(const uint4*)(src + (size_t)r * CDIM + k0 + slot * 8);
            *(uint4*)(sArr[a] + row * LDS_PAD + slot * 8) = v;
        }
        __syncthreads();

        // ---- compute: 4 x k16 steps ----
#pragma unroll
        for (int ks = 0; ks < 4; ks++) {
            const int kb = ks * 16;
            uint32_t bh[4][4], bl[4][4];
#pragma unroll
            for (int g = 0; g < 4; g++) {
                uint32_t off = ((warp_n * 64 + g * 16 + b_row) * LDS_PAD + kb + b_koff) * 2;
                LDSM_X4(bh[g][0], bh[g][1], bh[g][2], bh[g][3], sB_hi + off);
                LDSM_X4(bl[g][0], bl[g][1], bl[g][2], bl[g][3], sB_lo + off);
            }
            uint32_t af[2][4];
#pragma unroll
            for (int mt = 0; mt < 2; mt++) {
                uint32_t off = ((warp_m * 32 + mt * 16 + a_row) * LDS_PAD + kb + a_koff) * 2;
                LDSM_X4(af[mt][0], af[mt][1], af[mt][2], af[mt][3], sA_hi + off);
            }
            // Ahi*Bhi and Ahi*Blo
#pragma unroll
            for (int mt = 0; mt < 2; mt++)
#pragma unroll
                for (int g = 0; g < 4; g++) {
                    MMA16816(acc[mt][2 * g],     af[mt], bh[g][0], bh[g][1]);
                    MMA16816(acc[mt][2 * g + 1], af[mt], bh[g][2], bh[g][3]);
                    MMA16816(acc[mt][2 * g],     af[mt], bl[g][0], bl[g][1]);
                    MMA16816(acc[mt][2 * g + 1], af[mt], bl[g][2], bl[g][3]);
                }
            // Alo*Bhi
#pragma unroll
            for (int mt = 0; mt < 2; mt++) {
                uint32_t off = ((warp_m * 32 + mt * 16 + a_row) * LDS_PAD + kb + a_koff) * 2;
                LDSM_X4(af[mt][0], af[mt][1], af[mt][2], af[mt][3], sA_lo + off);
            }
#pragma unroll
            for (int mt = 0; mt < 2; mt++)
#pragma unroll
                for (int g = 0; g < 4; g++) {
                    MMA16816(acc[mt][2 * g],     af[mt], bh[g][0], bh[g][1]);
                    MMA16816(acc[mt][2 * g + 1], af[mt], bh[g][2], bh[g][3]);
                }
        }
        __syncthreads();
    }

    // ---- epilogue ----
    const int qrow = lane >> 2, qcol = (lane & 3) * 2;
#pragma unroll
    for (int mt = 0; mt < 2; mt++) {
#pragma unroll
        for (int half = 0; half < 2; half++) {
            int r = bm + warp_m * 32 + mt * 16 + qrow + half * 8;
            if (r >= M) continue;
#pragma unroll
            for (int nt = 0; nt < 8; nt++) {
                int cc = bn + warp_n * 64 + nt * 8 + qcol;
                float2 o;
                o.x = acc[mt][nt][2 * half]     * alpha + (bias ? bias[cc]     : 0.f);
                o.y = acc[mt][nt][2 * half + 1] * alpha + (bias ? bias[cc + 1] : 0.f);
                *(float2*)(C + (size_t)r * N + cc) = o;
            }
        }
    }
}

// ---------------------------------------------------------------------------
// Fused attention per (b, h, 64-row query tile). Register-tiled 4x13 QK^T,
// 16-lane shuffle softmax, P in smem, 4x4 PV. Writes AO directly as bf16
// hi/lo for the projection GEMM. Scores pre-scaled by 1/8 (folded into Q).
// ---------------------------------------------------------------------------
#define LDK 68
#define ATTN_SMEM_FLOATS (64 * LDK + 2 * MPAD * LDK + 64 * MPAD)

__global__ __launch_bounds__(256) void attn_kernel() {
    extern __shared__ float sm[];
    float* Qs = sm;                    // 64  x 68
    float* Ks = Qs + 64 * LDK;         // 208 x 68 (rows 204..207 zero)
    float* Vs = Ks + MPAD * LDK;       // 208 x 68
    float* Ps = Vs + MPAD * LDK;       // 64  x 208

    const int b = blockIdx.z, hidx = blockIdx.y;
    const int n0 = blockIdx.x * 64;
    const int tid = threadIdx.x;

    for (int i = tid; i < MPAD * 16; i += 256) {
        int m = i >> 4, q = i & 15;
        float4 kv = make_float4(0.f, 0.f, 0.f, 0.f), vv = kv;
        if (m < MG) {
            const float* base = g_KV + (size_t)(b * MG + m) * (2 * CDIM) + hidx * HD;
            kv = ((const float4*)base)[q];
            vv = ((const float4*)(base + CDIM))[q];
        }
        ((float4*)(Ks + m * LDK))[q] = kv;
        ((float4*)(Vs + m * LDK))[q] = vv;
    }
    for (int i = tid; i < 64 * 16; i += 256) {
        int r = i >> 4, q = i & 15;
        int n = n0 + r;
        float4 v = make_float4(0.f, 0.f, 0.f, 0.f);
        if (n < NTOK)
            v = ((const float4*)(g_Q + (size_t)(b * NTOK + n) * CDIM + hidx * HD))[q];
        ((float4*)(Qs + r * LDK))[q] = v;
    }
    __syncthreads();

    const int ti = tid >> 4, tj = tid & 15;
    const int r0 = ti * 4, c0 = tj * 13;

    float acc[4][13];
#pragma unroll
    for (int i = 0; i < 4; i++)
#pragma unroll
        for (int j = 0; j < 13; j++) acc[i][j] = 0.f;

    for (int d0 = 0; d0 < 64; d0 += 4) {
        float4 q4[4];
#pragma unroll
        for (int i = 0; i < 4; i++)
            q4[i] = *(const float4*)(Qs + (r0 + i) * LDK + d0);
#pragma unroll
        for (int j = 0; j < 13; j++) {
            float4 k4 = *(const float4*)(Ks + (c0 + j) * LDK + d0);
#pragma unroll
            for (int i = 0; i < 4; i++)
                acc[i][j] += q4[i].x * k4.x + q4[i].y * k4.y
                           + q4[i].z * k4.z + q4[i].w * k4.w;
        }
    }

    int fcol[13];          // -1 = cls (mask 1.0), -2 = pad
#pragma unroll
    for (int j = 0; j < 13; j++) {
        int m = c0 + j;
        if (m < NFR) fcol[j] = -1;
        else if (m < MG) {
            int mm = m - NFR;
            fcol[j] = (mm < 100) ? mm / 25 : 4 + (mm - 100) / 24;
        } else fcol[j] = -2;
    }

#pragma unroll
    for (int i = 0; i < 4; i++) {
        int n = n0 + r0 + i;
        int nf = (n < NTOK) ? n / NO : 0;
        float mx = -1e30f;
#pragma unroll
        for (int j = 0; j < 13; j++) {
            float s = acc[i][j];
            if (fcol[j] == -2) s = -1e30f;
            else if (fcol[j] >= 0 && fcol[j] != nf) s *= 0.8f;
            acc[i][j] = s;
            mx = fmaxf(mx, s);
        }
        mx = fmaxf(mx, __shfl_xor_sync(0xffffffffu, mx, 1));
        mx = fmaxf(mx, __shfl_xor_sync(0xffffffffu, mx, 2));
        mx = fmaxf(mx, __shfl_xor_sync(0xffffffffu, mx, 4));
        mx = fmaxf(mx, __shfl_xor_sync(0xffffffffu, mx, 8));
        float sum = 0.f;
#pragma unroll
        for (int j = 0; j < 13; j++) {
            float e = __expf(acc[i][j] - mx);
            acc[i][j] = e; sum += e;
        }
        sum += __shfl_xor_sync(0xffffffffu, sum, 1);
        sum += __shfl_xor_sync(0xffffffffu, sum, 2);
        sum += __shfl_xor_sync(0xffffffffu, sum, 4);
        sum += __shfl_xor_sync(0xffffffffu, sum, 8);
        float inv = 1.f / sum;
#pragma unroll
        for (int j = 0; j < 13; j++)
            Ps[(r0 + i) * MPAD + c0 + j] = acc[i][j] * inv;
    }
    __syncthreads();

    const int d0v = tj * 4;
    float o[4][4];
#pragma unroll
    for (int i = 0; i < 4; i++)
#pragma unroll
        for (int k = 0; k < 4; k++) o[i][k] = 0.f;

#pragma unroll 2
    for (int m = 0; m < MPAD; m++) {
        float4 v4 = *(const float4*)(Vs + m * LDK + d0v);
#pragma unroll
        for (int i = 0; i < 4; i++) {
            float p = Ps[(r0 + i) * MPAD + m];
            o[i][0] += p * v4.x; o[i][1] += p * v4.y;
            o[i][2] += p * v4.z; o[i][3] += p * v4.w;
        }
    }
#pragma unroll
    for (int i = 0; i < 4; i++) {
        int n = n0 + r0 + i;
        if (n >= NTOK) continue;
        size_t off = (size_t)(b * NTOK + n) * CDIM + hidx * HD + d0v;
        __nv_bfloat16 hh[4], ll[4];
#pragma unroll
        for (int k = 0; k < 4; k++) {
            hh[k] = __float2bfloat16(o[i][k]);
            ll[k] = __float2bfloat16(o[i][k] - __bfloat162float(hh[k]));
        }
        __nv_bfloat162 h0, h1, l0, l1;
        h0.x = hh[0]; h0.y = hh[1]; h1.x = hh[2]; h1.y = hh[3];
        l0.x = ll[0]; l0.y = ll[1]; l1.x = ll[2]; l1.y = ll[3];
        ((__nv_bfloat162*)(g_AOhi + off))[0] = h0;
        ((__nv_bfloat162*)(g_AOhi + off))[1] = h1;
        ((__nv_bfloat162*)(g_AOlo + off))[0] = l0;
        ((__nv_bfloat162*)(g_AOlo + off))[1] = l1;
    }
}

// ---------------------------------------------------------------------------
extern "C" void kernel_launch(void* const* d_in, const int* in_sizes, int n_in,
                              void* d_out, int out_size) {
    const float* x      = (const float*)d_in[0];
    const float* qkv_w  = (const float*)d_in[1];
    const float* proj_w = (const float*)d_in[2];
    const float* proj_b = (const float*)d_in[3];
    float* out = (float*)d_out;

    float *pQ, *pKV;
    __nv_bfloat16 *pXhi, *pXlo, *pWhi, *pWlo, *pPhi, *pPlo, *pAOhi, *pAOlo;
    cudaGetSymbolAddress((void**)&pQ, g_Q);
    cudaGetSymbolAddress((void**)&pKV, g_KV);
    cudaGetSymbolAddress((void**)&pXhi, g_Xhi);
    cudaGetSymbolAddress((void**)&pXlo, g_Xlo);
    cudaGetSymbolAddress((void**)&pWhi, g_Whi);
    cudaGetSymbolAddress((void**)&pWlo, g_Wlo);
    cudaGetSymbolAddress((void**)&pPhi, g_Phi);
    cudaGetSymbolAddress((void**)&pPlo, g_Plo);
    cudaGetSymbolAddress((void**)&pAOhi, g_AOhi);
    cudaGetSymbolAddress((void**)&pAOlo, g_AOlo);

    cudaFuncSetAttribute(gemm_mma, cudaFuncAttributeMaxDynamicSharedMemorySize, GEMM_SMEM);
    cudaFuncSetAttribute(attn_kernel, cudaFuncAttributeMaxDynamicSharedMemorySize,
                         ATTN_SMEM_FLOATS * 4);

    init_idx_kernel<<<1, 256>>>();

    int n4x = ROWS_X * CDIM / 4;
    int n4w = 3 * CDIM * CDIM / 4;
    int n4p = CDIM * CDIM / 4;
    cvt_kernel<<<(n4x + 255) / 256, 256>>>(x, pXhi, pXlo, n4x);
    cvt_kernel<<<(n4w + 255) / 256, 256>>>(qkv_w, pWhi, pWlo, n4w);
    cvt_kernel<<<(n4p + 255) / 256, 256>>>(proj_w, pPhi, pPlo, n4p);

    // Q = X @ Wq^T * 0.125
    dim3 gq(CDIM / 128, (ROWS_X + 127) / 128);
    gemm_mma<<<gq, 256, GEMM_SMEM>>>(pXhi, pXlo, pWhi, pWlo, pQ,
                                     ROWS_X, CDIM, nullptr, 0.125f, 0);
    // [K|V] on gathered rows (1632 x 1536)
    dim3 gkv(1536 / 128, (ROWS_KV + 127) / 128);
    gemm_mma<<<gkv, 256, GEMM_SMEM>>>(pXhi, pXlo,
                                      pWhi + CDIM * CDIM, pWlo + CDIM * CDIM, pKV,
                                      ROWS_KV, 2 * CDIM, nullptr, 1.f, 1);
    // fused attention -> bf16 hi/lo AO
    dim3 ga((NTOK + 63) / 64, NH, NB);
    attn_kernel<<<ga, 256, ATTN_SMEM_FLOATS * 4>>>();

    // out = AO @ proj_w^T + proj_b
    gemm_mma<<<gq, 256, GEMM_SMEM>>>(pAOhi, pAOlo, pPhi, pPlo, out,
                                     ROWS_X, CDIM, proj_b, 1.f, 0);
}

// round 6
// speedup vs baseline: 2.6505x; 2.1137x over previous
#include <cuda_runtime.h>
#include <cuda_fp16.h>
#include <cstdint>

#define NFR 8
#define NO 197
#define NB 8
#define NTOK 1576          // 8*197
#define CDIM 768
#define NH 12
#define HD 64
#define MG 204             // gathered tokens
#define MPAD 208
#define ROWS_X 12608       // 64*197
#define ROWS_KV 1632       // 8*204

// ---------------- scratch (no allocs allowed -> device globals) -------------
__device__ float g_Q[ROWS_X * CDIM];
__device__ float g_KV[ROWS_KV * 2 * CDIM];
__device__ int   g_idx[MG];
__device__ __half g_Xh[ROWS_X * CDIM];
__device__ __half g_Wh[3 * CDIM * CDIM];
__device__ __half g_Wl[3 * CDIM * CDIM];
__device__ __half g_Ph[CDIM * CDIM];
__device__ __half g_Pl[CDIM * CDIM];
__device__ __half g_AOh[ROWS_X * CDIM];

// ---------------------------------------------------------------------------
__global__ void init_idx_kernel() {
    int m = threadIdx.x;
    if (m >= MG) return;
    if (m < NFR) { g_idx[m] = m * NO; return; }
    int mm = m - NFR;
    int f, j;
    if (mm < 100) { f = mm / 25; j = mm - f * 25; }
    else          { f = 4 + (mm - 100) / 24; j = (mm - 100) - (f - 4) * 24; }
    g_idx[m] = f * NO + 1 + f + 8 * j;
}

// fp32 -> fp16 (hi only)
__global__ void cvt_hi_kernel(const float* __restrict__ src,
                              __half* __restrict__ hi, int n4) {
    int i = blockIdx.x * blockDim.x + threadIdx.x;
    if (i >= n4) return;
    float4 v = ((const float4*)src)[i];
    __half2 h0, h1;
    h0.x = __float2half(v.x); h0.y = __float2half(v.y);
    h1.x = __float2half(v.z); h1.y = __float2half(v.w);
    ((__half2*)hi)[2 * i]     = h0;
    ((__half2*)hi)[2 * i + 1] = h1;
}

// fp32 -> (fp16 hi, fp16 lo)
__global__ void cvt_split_kernel(const float* __restrict__ src,
                                 __half* __restrict__ hi,
                                 __half* __restrict__ lo, int n4) {
    int i = blockIdx.x * blockDim.x + threadIdx.x;
    if (i >= n4) return;
    float4 v = ((const float4*)src)[i];
    float f[4] = {v.x, v.y, v.z, v.w};
    __half hh[4], ll[4];
#pragma unroll
    for (int k = 0; k < 4; k++) {
        hh[k] = __float2half(f[k]);
        ll[k] = __float2half(f[k] - __half2float(hh[k]));
    }
    __half2 h0, h1, l0, l1;
    h0.x = hh[0]; h0.y = hh[1]; h1.x = hh[2]; h1.y = hh[3];
    l0.x = ll[0]; l0.y = ll[1]; l1.x = ll[2]; l1.y = ll[3];
    ((__half2*)hi)[2 * i]     = h0;
    ((__half2*)hi)[2 * i + 1] = h1;
    ((__half2*)lo)[2 * i]     = l0;
    ((__half2*)lo)[2 * i + 1] = l1;
}

// ---------------------------------------------------------------------------
// warp-mma helpers (base sm_103 PTX -- tcgen05 is a-gated, unavailable here)
// ---------------------------------------------------------------------------
__device__ __forceinline__ uint32_t smem_u32(const void* p) {
    uint32_t a;
    asm("{ .reg .u64 t; cvta.to.shared.u64 t, %1; cvt.u32.u64 %0, t; }"
        : "=r"(a) : "l"(p));
    return a;
}
#define LDSM_X4(r0, r1, r2, r3, addr)                                        \
    asm volatile("ldmatrix.sync.aligned.m8n8.x4.shared.b16 {%0,%1,%2,%3}, [%4];" \
                 : "=r"(r0), "=r"(r1), "=r"(r2), "=r"(r3) : "r"(addr))
#define MMA16816(d, a, b0, b1)                                               \
    asm volatile("mma.sync.aligned.m16n8k16.row.col.f32.f16.f16.f32 "        \
                 "{%0,%1,%2,%3}, {%4,%5,%6,%7}, {%8,%9}, {%0,%1,%2,%3};"     \
                 : "+f"((d)[0]), "+f"((d)[1]), "+f"((d)[2]), "+f"((d)[3])    \
                 : "r"((a)[0]), "r"((a)[1]), "r"((a)[2]), "r"((a)[3]),       \
                   "r"(b0), "r"(b1))
#define CP_ASYNC16(dst, src)                                                 \
    asm volatile("cp.async.cg.shared.global [%0], [%1], 16;"                 \
                 :: "r"(dst), "l"(src))
#define CP_COMMIT()  asm volatile("cp.async.commit_group;" ::: "memory")
#define CP_WAIT0()   asm volatile("cp.async.wait_group 0;" ::: "memory")

// ---------------------------------------------------------------------------
// C[M,N] = alpha * A[M,768] @ W[N,768]^T + bias, fp16 2-product:
//   C = Ah*Bh + Ah*Bl  (A residual dropped: ~1.4e-4 norm rel err)
// 128x128 CTA tile, BK=64, 8 warps (32x64 each), cp.async double-buffered.
// smem rows padded to 72 halves (144B) -> conflict-free ldmatrix.
// gather!=0: logical A row r -> (r/204)*1576 + g_idx[r%204]
// ---------------------------------------------------------------------------
#define LDS_PAD 72
#define ARR_ELEMS (128 * LDS_PAD)
#define BUF_ELEMS (3 * ARR_ELEMS)          // Ah | Bh | Bl
#define GEMM_SMEM (2 * BUF_ELEMS * 2)      // double buffer, bytes

__global__ __launch_bounds__(256)
void gemm_mma(const __half* __restrict__ Ah,
              const __half* __restrict__ Bh, const __half* __restrict__ Bl,
              float* __restrict__ C, int M, int N,
              const float* __restrict__ bias, float alpha, int gather)
{
    extern __shared__ __half smem[];
    const int tid = threadIdx.x;
    const int wid = tid >> 5, lane = tid & 31;
    const int bm = blockIdx.y * 128, bn = blockIdx.x * 128;
    const int warp_m = wid & 3, warp_n = wid >> 2;
    const uint32_t sbase = smem_u32(smem);

    float acc[2][8][4];
#pragma unroll
    for (int mt = 0; mt < 2; mt++)
#pragma unroll
        for (int nt = 0; nt < 8; nt++)
#pragma unroll
            for (int e = 0; e < 4; e++) acc[mt][nt][e] = 0.f;

    // ldmatrix lane address components
    const int a_row  = lane & 15;
    const int a_koff = (lane >> 4) << 3;
    const int b_row  = ((lane >> 4) << 3) + (lane & 7);
    const int b_koff = ((lane >> 3) & 1) << 3;

    // Precompute this thread's 12 (array,row,slot) staging slots
    // i = tid + 256*t, t in [0,12): a = i>>10, row = (i>>3)&127, slot = i&7
    // stage chunk `c` into buffer `buf`
    auto stage = [&](int c, int buf) {
        const int k0 = c * 64;
#pragma unroll
        for (int t = 0; t < 12; t++) {
            int i = tid + 256 * t;
            int a = i >> 10, row = (i >> 3) & 127, slot = i & 7;
            const __half* src;
            int r;
            if (a == 0) {
                r = bm + row; if (r >= M) r = 0;
                if (gather) { int bb = r / MG; int mm = r - bb * MG; r = bb * NTOK + g_idx[mm]; }
                src = Ah;
            } else {
                r = bn + row;
                src = (a == 1) ? Bh : Bl;
            }
            uint32_t dst = sbase +
                (uint32_t)(buf * BUF_ELEMS + a * ARR_ELEMS + row * LDS_PAD + slot * 8) * 2;
            CP_ASYNC16(dst, src + (size_t)r * CDIM + k0 + slot * 8);
        }
        CP_COMMIT();
    };

    stage(0, 0);

    for (int c = 0; c < 12; c++) {
        const int buf = c & 1;
        CP_WAIT0();
        __syncthreads();
        if (c + 1 < 12) stage(c + 1, buf ^ 1);

        const uint32_t sA  = sbase + (uint32_t)(buf * BUF_ELEMS) * 2;
        const uint32_t sBh = sA + ARR_ELEMS * 2;
        const uint32_t sBl = sA + 2 * ARR_ELEMS * 2;

#pragma unroll
        for (int ks = 0; ks < 4; ks++) {
            const int kb = ks * 16;
            uint32_t bh[4][4], bl[4][4], af[2][4];
#pragma unroll
            for (int g = 0; g < 4; g++) {
                uint32_t off = (uint32_t)((warp_n * 64 + g * 16 + b_row) * LDS_PAD + kb + b_koff) * 2;
                LDSM_X4(bh[g][0], bh[g][1], bh[g][2], bh[g][3], sBh + off);
                LDSM_X4(bl[g][0], bl[g][1], bl[g][2], bl[g][3], sBl + off);
            }
#pragma unroll
            for (int mt = 0; mt < 2; mt++) {
                uint32_t off = (uint32_t)((warp_m * 32 + mt * 16 + a_row) * LDS_PAD + kb + a_koff) * 2;
                LDSM_X4(af[mt][0], af[mt][1], af[mt][2], af[mt][3], sA + off);
            }
#pragma unroll
            for (int mt = 0; mt < 2; mt++)
#pragma unroll
                for (int g = 0; g < 4; g++) {
                    MMA16816(acc[mt][2 * g],     af[mt], bh[g][0], bh[g][1]);
                    MMA16816(acc[mt][2 * g + 1], af[mt], bh[g][2], bh[g][3]);
                    MMA16816(acc[mt][2 * g],     af[mt], bl[g][0], bl[g][1]);
                    MMA16816(acc[mt][2 * g + 1], af[mt], bl[g][2], bl[g][3]);
                }
        }
        __syncthreads();
    }

    // ---- epilogue ----
    const int qrow = lane >> 2, qcol = (lane & 3) * 2;
#pragma unroll
    for (int mt = 0; mt < 2; mt++) {
#pragma unroll
        for (int half = 0; half < 2; half++) {
            int r = bm + warp_m * 32 + mt * 16 + qrow + half * 8;
            if (r >= M) continue;
#pragma unroll
            for (int nt = 0; nt < 8; nt++) {
                int cc = bn + warp_n * 64 + nt * 8 + qcol;
                float2 o;
                o.x = acc[mt][nt][2 * half]     * alpha + (bias ? bias[cc]     : 0.f);
                o.y = acc[mt][nt][2 * half + 1] * alpha + (bias ? bias[cc + 1] : 0.f);
                *(float2*)(C + (size_t)r * N + cc) = o;
            }
        }
    }
}

// ---------------------------------------------------------------------------
// Fused attention per (b, h, 64-row query tile). Register-tiled 4x13 QK^T,
// 16-lane shuffle softmax, P in smem, 4x4 PV. Writes AO directly as fp16
// (A-side of proj GEMM needs hi only). Scores pre-scaled by 1/8.
// ---------------------------------------------------------------------------
#define LDK 68
#define ATTN_SMEM_FLOATS (64 * LDK + 2 * MPAD * LDK + 64 * MPAD)

__global__ __launch_bounds__(256) void attn_kernel() {
    extern __shared__ float sm[];
    float* Qs = sm;                    // 64  x 68
    float* Ks = Qs + 64 * LDK;         // 208 x 68 (rows 204..207 zero)
    float* Vs = Ks + MPAD * LDK;       // 208 x 68
    float* Ps = Vs + MPAD * LDK;       // 64  x 208

    const int b = blockIdx.z, hidx = blockIdx.y;
    const int n0 = blockIdx.x * 64;
    const int tid = threadIdx.x;

    for (int i = tid; i < MPAD * 16; i += 256) {
        int m = i >> 4, q = i & 15;
        float4 kv = make_float4(0.f, 0.f, 0.f, 0.f), vv = kv;
        if (m < MG) {
            const float* base = g_KV + (size_t)(b * MG + m) * (2 * CDIM) + hidx * HD;
            kv = ((const float4*)base)[q];
            vv = ((const float4*)(base + CDIM))[q];
        }
        ((float4*)(Ks + m * LDK))[q] = kv;
        ((float4*)(Vs + m * LDK))[q] = vv;
    }
    for (int i = tid; i < 64 * 16; i += 256) {
        int r = i >> 4, q = i & 15;
        int n = n0 + r;
        float4 v = make_float4(0.f, 0.f, 0.f, 0.f);
        if (n < NTOK)
            v = ((const float4*)(g_Q + (size_t)(b * NTOK + n) * CDIM + hidx * HD))[q];
        ((float4*)(Qs + r * LDK))[q] = v;
    }
    __syncthreads();

    const int ti = tid >> 4, tj = tid & 15;
    const int r0 = ti * 4, c0 = tj * 13;

    float acc[4][13];
#pragma unroll
    for (int i = 0; i < 4; i++)
#pragma unroll
        for (int j = 0; j < 13; j++) acc[i][j] = 0.f;

    for (int d0 = 0; d0 < 64; d0 += 4) {
        float4 q4[4];
#pragma unroll
        for (int i = 0; i < 4; i++)
            q4[i] = *(const float4*)(Qs + (r0 + i) * LDK + d0);
#pragma unroll
        for (int j = 0; j < 13; j++) {
            float4 k4 = *(const float4*)(Ks + (c0 + j) * LDK + d0);
#pragma unroll
            for (int i = 0; i < 4; i++)
                acc[i][j] += q4[i].x * k4.x + q4[i].y * k4.y
                           + q4[i].z * k4.z + q4[i].w * k4.w;
        }
    }

    int fcol[13];          // -1 = cls (mask 1.0), -2 = pad
#pragma unroll
    for (int j = 0; j < 13; j++) {
        int m = c0 + j;
        if (m < NFR) fcol[j] = -1;
        else if (m < MG) {
            int mm = m - NFR;
            fcol[j] = (mm < 100) ? mm / 25 : 4 + (mm - 100) / 24;
        } else fcol[j] = -2;
    }

#pragma unroll
    for (int i = 0; i < 4; i++) {
        int n = n0 + r0 + i;
        int nf = (n < NTOK) ? n / NO : 0;
        float mx = -1e30f;
#pragma unroll
        for (int j = 0; j < 13; j++) {
            float s = acc[i][j];
            if (fcol[j] == -2) s = -1e30f;
            else if (fcol[j] >= 0 && fcol[j] != nf) s *= 0.8f;
            acc[i][j] = s;
            mx = fmaxf(mx, s);
        }
        mx = fmaxf(mx, __shfl_xor_sync(0xffffffffu, mx, 1));
        mx = fmaxf(mx, __shfl_xor_sync(0xffffffffu, mx, 2));
        mx = fmaxf(mx, __shfl_xor_sync(0xffffffffu, mx, 4));
        mx = fmaxf(mx, __shfl_xor_sync(0xffffffffu, mx, 8));
        float sum = 0.f;
#pragma unroll
        for (int j = 0; j < 13; j++) {
            float e = __expf(acc[i][j] - mx);
            acc[i][j] = e; sum += e;
        }
        sum += __shfl_xor_sync(0xffffffffu, sum, 1);
        sum += __shfl_xor_sync(0xffffffffu, sum, 2);
        sum += __shfl_xor_sync(0xffffffffu, sum, 4);
        sum += __shfl_xor_sync(0xffffffffu, sum, 8);
        float inv = 1.f / sum;
#pragma unroll
        for (int j = 0; j < 13; j++)
            Ps[(r0 + i) * MPAD + c0 + j] = acc[i][j] * inv;
    }
    __syncthreads();

    const int d0v = tj * 4;
    float o[4][4];
#pragma unroll
    for (int i = 0; i < 4; i++)
#pragma unroll
        for (int k = 0; k < 4; k++) o[i][k] = 0.f;

#pragma unroll 2
    for (int m = 0; m < MPAD; m++) {
        float4 v4 = *(const float4*)(Vs + m * LDK + d0v);
#pragma unroll
        for (int i = 0; i < 4; i++) {
            float p = Ps[(r0 + i) * MPAD + m];
            o[i][0] += p * v4.x; o[i][1] += p * v4.y;
            o[i][2] += p * v4.z; o[i][3] += p * v4.w;
        }
    }
#pragma unroll
    for (int i = 0; i < 4; i++) {
        int n = n0 + r0 + i;
        if (n >= NTOK) continue;
        size_t off = (size_t)(b * NTOK + n) * CDIM + hidx * HD + d0v;
        __half2 h0, h1;
        h0.x = __float2half(o[i][0]); h0.y = __float2half(o[i][1]);
        h1.x = __float2half(o[i][2]); h1.y = __float2half(o[i][3]);
        ((__half2*)(g_AOh + off))[0] = h0;
        ((__half2*)(g_AOh + off))[1] = h1;
    }
}

// ---------------------------------------------------------------------------
extern "C" void kernel_launch(void* const* d_in, const int* in_sizes, int n_in,
                              void* d_out, int out_size) {
    const float* x      = (const float*)d_in[0];
    const float* qkv_w  = (const float*)d_in[1];
    const float* proj_w = (const float*)d_in[2];
    const float* proj_b = (const float*)d_in[3];
    float* out = (float*)d_out;

    float *pQ, *pKV;
    __half *pXh, *pWh, *pWl, *pPh, *pPl, *pAOh;
    cudaGetSymbolAddress((void**)&pQ, g_Q);
    cudaGetSymbolAddress((void**)&pKV, g_KV);
    cudaGetSymbolAddress((void**)&pXh, g_Xh);
    cudaGetSymbolAddress((void**)&pWh, g_Wh);
    cudaGetSymbolAddress((void**)&pWl, g_Wl);
    cudaGetSymbolAddress((void**)&pPh, g_Ph);
    cudaGetSymbolAddress((void**)&pPl, g_Pl);
    cudaGetSymbolAddress((void**)&pAOh, g_AOh);

    cudaFuncSetAttribute(gemm_mma, cudaFuncAttributeMaxDynamicSharedMemorySize, GEMM_SMEM);
    cudaFuncSetAttribute(attn_kernel, cudaFuncAttributeMaxDynamicSharedMemorySize,
                         ATTN_SMEM_FLOATS * 4);

    init_idx_kernel<<<1, 256>>>();

    int n4x = ROWS_X * CDIM / 4;
    int n4w = 3 * CDIM * CDIM / 4;
    int n4p = CDIM * CDIM / 4;
    cvt_hi_kernel<<<(n4x + 255) / 256, 256>>>(x, pXh, n4x);
    cvt_split_kernel<<<(n4w + 255) / 256, 256>>>(qkv_w, pWh, pWl, n4w);
    cvt_split_kernel<<<(n4p + 255) / 256, 256>>>(proj_w, pPh, pPl, n4p);

    // Q = X @ Wq^T * 0.125
    dim3 gq(CDIM / 128, (ROWS_X + 127) / 128);
    gemm_mma<<<gq, 256, GEMM_SMEM>>>(pXh, pWh, pWl, pQ,
                                     ROWS_X, CDIM, nullptr, 0.125f, 0);
    // [K|V] on gathered rows (1632 x 1536)
    dim3 gkv(1536 / 128, (ROWS_KV + 127) / 128);
    gemm_mma<<<gkv, 256, GEMM_SMEM>>>(pXh,
                                      pWh + CDIM * CDIM, pWl + CDIM * CDIM, pKV,
                                      ROWS_KV, 2 * CDIM, nullptr, 1.f, 1);
    // fused attention -> fp16 AO
    dim3 ga((NTOK + 63) / 64, NH, NB);
    attn_kernel<<<ga, 256, ATTN_SMEM_FLOATS * 4>>>();

    // out = AO @ proj_w^T + proj_b
    gemm_mma<<<gq, 256, GEMM_SMEM>>>(pAOh, pPh, pPl, out,
                                     ROWS_X, CDIM, proj_b, 1.f, 0);
}

// round 8
// speedup vs baseline: 5.3723x; 2.0269x over previous
#include <cuda_runtime.h>
#include <cuda_fp16.h>
#include <cstdint>

#define NFR 8
#define NO 197
#define NB 8
#define NTOK 1576          // 8*197
#define CDIM 768
#define NH 12
#define HD 64
#define MG 204             // gathered tokens
#define ROWS_X 12608       // 64*197
#define ROWS_KV 1632       // 8*204

// ---------------- scratch (no allocs allowed -> device globals) -------------
__device__ int    g_idx[MG];
__device__ __half g_Xh[ROWS_X * CDIM];
__device__ __half g_Wh[3 * CDIM * CDIM];
__device__ __half g_Wl[3 * CDIM * CDIM];
__device__ __half g_Ph[CDIM * CDIM];
__device__ __half g_Pl[CDIM * CDIM];
__device__ __half g_Q16[ROWS_X * CDIM];        // Q projection (x0.125), fp16
__device__ __half g_KV16[ROWS_KV * 2 * CDIM];  // [K(768) | V(768)] fp16
__device__ __half g_AOh[ROWS_X * CDIM];

// ---------------------------------------------------------------------------
__global__ void init_idx_kernel() {
    int m = threadIdx.x;
    if (m >= MG) return;
    if (m < NFR) { g_idx[m] = m * NO; return; }
    int mm = m - NFR;
    int f, j;
    if (mm < 100) { f = mm / 25; j = mm - f * 25; }
    else          { f = 4 + (mm - 100) / 24; j = (mm - 100) - (f - 4) * 24; }
    g_idx[m] = f * NO + 1 + f + 8 * j;
}

// fp32 -> fp16 (hi only)
__global__ void cvt_hi_kernel(const float* __restrict__ src,
                              __half* __restrict__ hi, int n4) {
    int i = blockIdx.x * blockDim.x + threadIdx.x;
    if (i >= n4) return;
    float4 v = ((const float4*)src)[i];
    __half2 h0, h1;
    h0.x = __float2half(v.x); h0.y = __float2half(v.y);
    h1.x = __float2half(v.z); h1.y = __float2half(v.w);
    ((__half2*)hi)[2 * i]     = h0;
    ((__half2*)hi)[2 * i + 1] = h1;
}

// fp32 -> (fp16 hi, fp16 lo)
__global__ void cvt_split_kernel(const float* __restrict__ src,
                                 __half* __restrict__ hi,
                                 __half* __restrict__ lo, int n4) {
    int i = blockIdx.x * blockDim.x + threadIdx.x;
    if (i >= n4) return;
    float4 v = ((const float4*)src)[i];
    float f[4] = {v.x, v.y, v.z, v.w};
    __half hh[4], ll[4];
#pragma unroll
    for (int k = 0; k < 4; k++) {
        hh[k] = __float2half(f[k]);
        ll[k] = __float2half(f[k] - __half2float(hh[k]));
    }
    __half2 h0, h1, l0, l1;
    h0.x = hh[0]; h0.y = hh[1]; h1.x = hh[2]; h1.y = hh[3];
    l0.x = ll[0]; l0.y = ll[1]; l1.x = ll[2]; l1.y = ll[3];
    ((__half2*)hi)[2 * i]     = h0;
    ((__half2*)hi)[2 * i + 1] = h1;
    ((__half2*)lo)[2 * i]     = l0;
    ((__half2*)lo)[2 * i + 1] = l1;
}

// ---------------------------------------------------------------------------
// warp-mma helpers (base sm_103 PTX -- tcgen05 is a-gated, unavailable here)
// ---------------------------------------------------------------------------
__device__ __forceinline__ uint32_t smem_u32(const void* p) {
    uint32_t a;
    asm("{ .reg .u64 t; cvta.to.shared.u64 t, %1; cvt.u32.u64 %0, t; }"
        : "=r"(a) : "l"(p));
    return a;
}
#define LDSM_X4(r0, r1, r2, r3, addr)                                        \
    asm volatile("ldmatrix.sync.aligned.m8n8.x4.shared.b16 {%0,%1,%2,%3}, [%4];" \
                 : "=r"(r0), "=r"(r1), "=r"(r2), "=r"(r3) : "r"(addr))
#define LDSM_X4_T(r0, r1, r2, r3, addr)                                      \
    asm volatile("ldmatrix.sync.aligned.m8n8.x4.trans.shared.b16 {%0,%1,%2,%3}, [%4];" \
                 : "=r"(r0), "=r"(r1), "=r"(r2), "=r"(r3) : "r"(addr))
#define MMA16816(d, a, b0, b1)                                               \
    asm volatile("mma.sync.aligned.m16n8k16.row.col.f32.f16.f16.f32 "        \
                 "{%0,%1,%2,%3}, {%4,%5,%6,%7}, {%8,%9}, {%0,%1,%2,%3};"     \
                 : "+f"((d)[0]), "+f"((d)[1]), "+f"((d)[2]), "+f"((d)[3])    \
                 : "r"((a)[0]), "r"((a)[1]), "r"((a)[2]), "r"((a)[3]),       \
                   "r"(b0), "r"(b1))
#define CP_ASYNC16(dst, src)                                                 \
    asm volatile("cp.async.cg.shared.global [%0], [%1], 16;"                 \
                 :: "r"(dst), "l"(src))
#define CP_COMMIT()  asm volatile("cp.async.commit_group;" ::: "memory")
#define CP_WAIT0()   asm volatile("cp.async.wait_group 0;" ::: "memory")

// ---------------------------------------------------------------------------
// C[M,N] = alpha * A[M,768] @ W[N,768]^T + bias, fp16 2-product:
//   C = Ah*Bh + Ah*Bl.  out_half: write fp16 (no bias) instead of fp32.
// 128x128 CTA tile, BK=64, 8 warps (32x64 each), cp.async double-buffered.
// gather!=0: logical A row r -> (r/204)*1576 + g_idx[r%204]
// ---------------------------------------------------------------------------
#define LDS_PAD 72
#define ARR_ELEMS (128 * LDS_PAD)
#define BUF_ELEMS (3 * ARR_ELEMS)          // Ah | Bh | Bl
#define GEMM_SMEM (2 * BUF_ELEMS * 2)      // double buffer, bytes

__global__ __launch_bounds__(256)
void gemm_mma(const __half* __restrict__ Ah,
              const __half* __restrict__ Bh, const __half* __restrict__ Bl,
              void* __restrict__ Cout, int M, int N,
              const float* __restrict__ bias, float alpha, int gather,
              int out_half)
{
    extern __shared__ __half smem[];
    const int tid = threadIdx.x;
    const int wid = tid >> 5, lane = tid & 31;
    const int bm = blockIdx.y * 128, bn = blockIdx.x * 128;
    const int warp_m = wid & 3, warp_n = wid >> 2;
    const uint32_t sbase = smem_u32(smem);

    float acc[2][8][4];
#pragma unroll
    for (int mt = 0; mt < 2; mt++)
#pragma unroll
        for (int nt = 0; nt < 8; nt++)
#pragma unroll
            for (int e = 0; e < 4; e++) acc[mt][nt][e] = 0.f;

    const int a_row  = lane & 15;
    const int a_koff = (lane >> 4) << 3;
    const int b_row  = ((lane >> 4) << 3) + (lane & 7);
    const int b_koff = ((lane >> 3) & 1) << 3;

    auto stage = [&](int c, int buf) {
        const int k0 = c * 64;
#pragma unroll
        for (int t = 0; t < 12; t++) {
            int i = tid + 256 * t;
            int a = i >> 10, row = (i >> 3) & 127, slot = i & 7;
            const __half* src;
            int r;
            if (a == 0) {
                r = bm + row; if (r >= M) r = 0;
                if (gather) { int bb = r / MG; int mm = r - bb * MG; r = bb * NTOK + g_idx[mm]; }
                src = Ah;
            } else {
                r = bn + row;
                src = (a == 1) ? Bh : Bl;
            }
            uint32_t dst = sbase +
                (uint32_t)(buf * BUF_ELEMS + a * ARR_ELEMS + row * LDS_PAD + slot * 8) * 2;
            CP_ASYNC16(dst, src + (size_t)r * CDIM + k0 + slot * 8);
        }
        CP_COMMIT();
    };

    stage(0, 0);

    for (int c = 0; c < 12; c++) {
        const int buf = c & 1;
        CP_WAIT0();
        __syncthreads();
        if (c + 1 < 12) stage(c + 1, buf ^ 1);

        const uint32_t sA  = sbase + (uint32_t)(buf * BUF_ELEMS) * 2;
        const uint32_t sBh = sA + ARR_ELEMS * 2;
        const uint32_t sBl = sA + 2 * ARR_ELEMS * 2;

#pragma unroll
        for (int ks = 0; ks < 4; ks++) {
            const int kb = ks * 16;
            uint32_t bh[4][4], bl[4][4], af[2][4];
#pragma unroll
            for (int g = 0; g < 4; g++) {
                uint32_t off = (uint32_t)((warp_n * 64 + g * 16 + b_row) * LDS_PAD + kb + b_koff) * 2;
                LDSM_X4(bh[g][0], bh[g][1], bh[g][2], bh[g][3], sBh + off);
                LDSM_X4(bl[g][0], bl[g][1], bl[g][2], bl[g][3], sBl + off);
            }
#pragma unroll
            for (int mt = 0; mt < 2; mt++) {
                uint32_t off = (uint32_t)((warp_m * 32 + mt * 16 + a_row) * LDS_PAD + kb + a_koff) * 2;
                LDSM_X4(af[mt][0], af[mt][1], af[mt][2], af[mt][3], sA + off);
            }
#pragma unroll
            for (int mt = 0; mt < 2; mt++)
#pragma unroll
                for (int g = 0; g < 4; g++) {
                    MMA16816(acc[mt][2 * g],     af[mt], bh[g][0], bh[g][1]);
                    MMA16816(acc[mt][2 * g + 1], af[mt], bh[g][2], bh[g][3]);
                    MMA16816(acc[mt][2 * g],     af[mt], bl[g][0], bl[g][1]);
                    MMA16816(acc[mt][2 * g + 1], af[mt], bl[g][2], bl[g][3]);
                }
        }
        __syncthreads();
    }

    // ---- epilogue ----
    const int qrow = lane >> 2, qcol = (lane & 3) * 2;
#pragma unroll
    for (int mt = 0; mt < 2; mt++) {
#pragma unroll
        for (int half = 0; half < 2; half++) {
            int r = bm + warp_m * 32 + mt * 16 + qrow + half * 8;
            if (r >= M) continue;
#pragma unroll
            for (int nt = 0; nt < 8; nt++) {
                int cc = bn + warp_n * 64 + nt * 8 + qcol;
                float ox = acc[mt][nt][2 * half]     * alpha;
                float oy = acc[mt][nt][2 * half + 1] * alpha;
                if (out_half) {
                    __half2 hv;
                    hv.x = __float2half(ox); hv.y = __float2half(oy);
                    *(__half2*)((__half*)Cout + (size_t)r * N + cc) = hv;
                } else {
                    float2 o;
                    o.x = ox + (bias ? bias[cc]     : 0.f);
                    o.y = oy + (bias ? bias[cc + 1] : 0.f);
                    *(float2*)((float*)Cout + (size_t)r * N + cc) = o;
                }
            }
        }
    }
}

// ---------------------------------------------------------------------------
// Tensor-core fused attention. Block = 128 threads (4 warps), one (b, h,
// 64-row q-tile). Warp w owns rows 16w..16w+15 over all 208 key columns
// (204 real + 4 masked pad). QK^T: 104 HMMA/warp. Softmax in fragment space
// (mask computed arithmetically; normalization deferred to epilogue).
// P fragments (m16n8 acc == m16k16 A layout) feed PV: 104 HMMA/warp with
// ldmatrix.trans on V. Output written fp16 to g_AOh.
// ---------------------------------------------------------------------------
#define ALD 72
#define ATTN_SMEM ((64 + 208 + 208) * ALD * 2)   // bytes

__global__ __launch_bounds__(128) void attn_mma_kernel() {
    extern __shared__ __half sm16[];
    const int b = blockIdx.z, h = blockIdx.y;
    const int n0 = blockIdx.x * 64;
    const int tid = threadIdx.x, w = tid >> 5, lane = tid & 31;
    const uint32_t sb = smem_u32(sm16);
    // layout: Q rows [0,64), K rows [64,272), V rows [272,480), stride ALD

    // ---- load Q (64x64) ----
#pragma unroll
    for (int t = 0; t < 4; t++) {
        int i = tid + 128 * t;           // [0,512)
        int r = i >> 3, q = i & 7;
        int n = n0 + r; if (n >= NTOK) n = NTOK - 1;
        const __half* src = g_Q16 + (size_t)(b * NTOK + n) * CDIM + h * HD + q * 8;
        CP_ASYNC16(sb + (uint32_t)(r * ALD + q * 8) * 2, src);
    }
    // ---- load K,V (208x64 each; rows >=204 clamped, masked later) ----
#pragma unroll
    for (int t = 0; t < 13; t++) {
        int i = tid + 128 * t;           // [0,1664)
        int m = i >> 3, q = i & 7;
        int mc = m < MG ? m : MG - 1;
        const __half* base = g_KV16 + (size_t)(b * MG + mc) * (2 * CDIM) + h * HD + q * 8;
        CP_ASYNC16(sb + (uint32_t)((64 + m) * ALD + q * 8) * 2, base);
        CP_ASYNC16(sb + (uint32_t)((272 + m) * ALD + q * 8) * 2, base + CDIM);
    }
    CP_COMMIT();
    CP_WAIT0();
    __syncthreads();

    const int a_row  = lane & 15;
    const int a_koff = (lane >> 4) << 3;
    const int b_row  = ((lane >> 4) << 3) + (lane & 7);
    const int b_koff = ((lane >> 3) & 1) << 3;

    // ---- QK^T: s[26 tiles][4] ----
    float s[26][4];
#pragma unroll
    for (int nt = 0; nt < 26; nt++)
#pragma unroll
        for (int e = 0; e < 4; e++) s[nt][e] = 0.f;

#pragma unroll
    for (int ks = 0; ks < 4; ks++) {
        const int kb = ks * 16;
        uint32_t af[4];
        LDSM_X4(af[0], af[1], af[2], af[3],
                sb + (uint32_t)((w * 16 + a_row) * ALD + kb + a_koff) * 2);
#pragma unroll
        for (int g = 0; g < 13; g++) {
            uint32_t b0, b1, b2, b3;
            LDSM_X4(b0, b1, b2, b3,
                    sb + (uint32_t)((64 + g * 16 + b_row) * ALD + kb + b_koff) * 2);
            MMA16816(s[2 * g],     af, b0, b1);
            MMA16816(s[2 * g + 1], af, b2, b3);
        }
    }

    // ---- mask + softmax (rows qrow, qrow+8) ----
    const int qrow = lane >> 2;
    const int nrow0 = n0 + w * 16 + qrow;
    const int nrow1 = nrow0 + 8;
    const int nf0 = (nrow0 < NTOK) ? nrow0 / NO : 0;
    const int nf1 = (nrow1 < NTOK) ? nrow1 / NO : 0;

    float mx0 = -1e30f, mx1 = -1e30f;
#pragma unroll
    for (int nt = 0; nt < 26; nt++) {
#pragma unroll
        for (int e = 0; e < 2; e++) {
            int c = nt * 8 + (lane & 3) * 2 + e;
            if (c >= MG) { s[nt][e] = -1e30f; s[nt][2 + e] = -1e30f; continue; }
            if (c >= NFR) {
                int mm = c - NFR;
                int f = (mm < 100) ? mm / 25 : 4 + (mm - 100) / 24;
                if (f != nf0) s[nt][e]     *= 0.8f;
                if (f != nf1) s[nt][2 + e] *= 0.8f;
            }
            mx0 = fmaxf(mx0, s[nt][e]);
            mx1 = fmaxf(mx1, s[nt][2 + e]);
        }
    }
    mx0 = fmaxf(mx0, __shfl_xor_sync(0xffffffffu, mx0, 1));
    mx0 = fmaxf(mx0, __shfl_xor_sync(0xffffffffu, mx0, 2));
    mx1 = fmaxf(mx1, __shfl_xor_sync(0xffffffffu, mx1, 1));
    mx1 = fmaxf(mx1, __shfl_xor_sync(0xffffffffu, mx1, 2));

    float sum0 = 0.f, sum1 = 0.f;
    uint32_t p2[26][2];
#pragma unroll
    for (int nt = 0; nt < 26; nt++) {
        float e0 = __expf(s[nt][0] - mx0);
        float e1 = __expf(s[nt][1] - mx0);
        float e2 = __expf(s[nt][2] - mx1);
        float e3 = __expf(s[nt][3] - mx1);
        sum0 += e0 + e1; sum1 += e2 + e3;
        __half2 lo, hi;
        lo.x = __float2half(e0); lo.y = __float2half(e1);
        hi.x = __float2half(e2); hi.y = __float2half(e3);
        p2[nt][0] = *(uint32_t*)&lo;
        p2[nt][1] = *(uint32_t*)&hi;
    }
    sum0 += __shfl_xor_sync(0xffffffffu, sum0, 1);
    sum0 += __shfl_xor_sync(0xffffffffu, sum0, 2);
    sum1 += __shfl_xor_sync(0xffffffffu, sum1, 1);
    sum1 += __shfl_xor_sync(0xffffffffu, sum1, 2);
    const float inv0 = 1.f / sum0, inv1 = 1.f / sum1;

    // ---- PV: out[16 x 64] += P[16 x 208] * V[208 x 64] ----
    float o[8][4];
#pragma unroll
    for (int nt = 0; nt < 8; nt++)
#pragma unroll
        for (int e = 0; e < 4; e++) o[nt][e] = 0.f;

#pragma unroll
    for (int ng = 0; ng < 4; ng++) {
#pragma unroll
        for (int kk = 0; kk < 13; kk++) {
            uint32_t v0, v1, v2, v3;
            LDSM_X4_T(v0, v1, v2, v3,
                      sb + (uint32_t)((272 + kk * 16 + (lane & 15)) * ALD
                                      + ng * 16 + ((lane >> 4) << 3)) * 2);
            uint32_t af[4] = { p2[2 * kk][0], p2[2 * kk][1],
                               p2[2 * kk + 1][0], p2[2 * kk + 1][1] };
            MMA16816(o[2 * ng],     af, v0, v1);
            MMA16816(o[2 * ng + 1], af, v2, v3);
        }
    }

    // ---- epilogue: normalize + fp16 store ----
    if (nrow0 < NTOK) {
        __half* dst = g_AOh + (size_t)(b * NTOK + nrow0) * CDIM + h * HD;
#pragma unroll
        for (int nt = 0; nt < 8; nt++) {
            int d = nt * 8 + (lane & 3) * 2;
            __half2 hv;
            hv.x = __float2half(o[nt][0] * inv0);
            hv.y = __float2half(o[nt][1] * inv0);
            *(__half2*)(dst + d) = hv;
        }
    }
    if (nrow1 < NTOK) {
        __half* dst = g_AOh + (size_t)(b * NTOK + nrow1) * CDIM + h * HD;
#pragma unroll
        for (int nt = 0; nt < 8; nt++) {
            int d = nt * 8 + (lane & 3) * 2;
            __half2 hv;
            hv.x = __float2half(o[nt][2] * inv1);
            hv.y = __float2half(o[nt][3] * inv1);
            *(__half2*)(dst + d) = hv;
        }
    }
}

// ---------------------------------------------------------------------------
extern "C" void kernel_launch(void* const* d_in, const int* in_sizes, int n_in,
                              void* d_out, int out_size) {
    const float* x      = (const float*)d_in[0];
    const float* qkv_w  = (const float*)d_in[1];
    const float* proj_w = (const float*)d_in[2];
    const float* proj_b = (const float*)d_in[3];
    float* out = (float*)d_out;

    __half *pXh, *pWh, *pWl, *pPh, *pPl, *pAOh, *pQ16, *pKV16;
    cudaGetSymbolAddress((void**)&pXh, g_Xh);
    cudaGetSymbolAddress((void**)&pWh, g_Wh);
    cudaGetSymbolAddress((void**)&pWl, g_Wl);
    cudaGetSymbolAddress((void**)&pPh, g_Ph);
    cudaGetSymbolAddress((void**)&pPl, g_Pl);
    cudaGetSymbolAddress((void**)&pAOh, g_AOh);
    cudaGetSymbolAddress((void**)&pQ16, g_Q16);
    cudaGetSymbolAddress((void**)&pKV16, g_KV16);

    cudaFuncSetAttribute(gemm_mma, cudaFuncAttributeMaxDynamicSharedMemorySize, GEMM_SMEM);
    cudaFuncSetAttribute(attn_mma_kernel, cudaFuncAttributeMaxDynamicSharedMemorySize,
                         ATTN_SMEM);

    init_idx_kernel<<<1, 256>>>();

    int n4x = ROWS_X * CDIM / 4;
    int n4w = 3 * CDIM * CDIM / 4;
    int n4p = CDIM * CDIM / 4;
    cvt_hi_kernel<<<(n4x + 255) / 256, 256>>>(x, pXh, n4x);
    cvt_split_kernel<<<(n4w + 255) / 256, 256>>>(qkv_w, pWh, pWl, n4w);
    cvt_split_kernel<<<(n4p + 255) / 256, 256>>>(proj_w, pPh, pPl, n4p);

    // Q16 = fp16( X @ Wq^T * 0.125 )
    dim3 gq(CDIM / 128, (ROWS_X + 127) / 128);
    gemm_mma<<<gq, 256, GEMM_SMEM>>>(pXh, pWh, pWl, pQ16,
                                     ROWS_X, CDIM, nullptr, 0.125f, 0, 1);
    // KV16 = fp16( gathered X @ [Wk|Wv]^T )   (1632 x 1536)
    dim3 gkv(1536 / 128, (ROWS_KV + 127) / 128);
    gemm_mma<<<gkv, 256, GEMM_SMEM>>>(pXh,
                                      pWh + CDIM * CDIM, pWl + CDIM * CDIM, pKV16,
                                      ROWS_KV, 2 * CDIM, nullptr, 1.f, 1, 1);
    // fused tensor-core attention -> fp16 AO
    dim3 ga((NTOK + 63) / 64, NH, NB);
    attn_mma_kernel<<<ga, 128, ATTN_SMEM>>>();

    // out = AO @ proj_w^T + proj_b  (fp32)
    gemm_mma<<<gq, 256, GEMM_SMEM>>>(pAOh, pPh, pPl, out,
                                     ROWS_X, CDIM, proj_b, 1.f, 0, 0);
}

// round 9
// speedup vs baseline: 7.4774x; 1.3919x over previous
#include <cuda_runtime.h>
#include <cuda_fp16.h>
#include <cstdint>

#define NFR 8
#define NO 197
#define NB 8
#define NTOK 1576          // 8*197
#define CDIM 768
#define NH 12
#define HD 64
#define MG 204             // gathered tokens
#define ROWS_X 12608       // 64*197
#define ROWS_KV 1632       // 8*204

// ---------------- scratch (no allocs allowed -> device globals) -------------
__device__ int    g_idx[MG];
__device__ __half g_Xh[ROWS_X * CDIM];
__device__ __half g_Wh[3 * CDIM * CDIM];
__device__ __half g_Ph[CDIM * CDIM];
__device__ __half g_Q16[ROWS_X * CDIM];        // Q projection (x0.125), fp16
__device__ __half g_KV16[ROWS_KV * 2 * CDIM];  // [K(768) | V(768)] fp16
__device__ __half g_AOh[ROWS_X * CDIM];

// ---------------------------------------------------------------------------
__global__ void init_idx_kernel() {
    int m = threadIdx.x;
    if (m >= MG) return;
    if (m < NFR) { g_idx[m] = m * NO; return; }
    int mm = m - NFR;
    int f, j;
    if (mm < 100) { f = mm / 25; j = mm - f * 25; }
    else          { f = 4 + (mm - 100) / 24; j = (mm - 100) - (f - 4) * 24; }
    g_idx[m] = f * NO + 1 + f + 8 * j;
}

// fp32 -> fp16
__global__ void cvt_hi_kernel(const float* __restrict__ src,
                              __half* __restrict__ hi, int n4) {
    int i = blockIdx.x * blockDim.x + threadIdx.x;
    if (i >= n4) return;
    float4 v = ((const float4*)src)[i];
    __half2 h0, h1;
    h0.x = __float2half(v.x); h0.y = __float2half(v.y);
    h1.x = __float2half(v.z); h1.y = __float2half(v.w);
    ((__half2*)hi)[2 * i]     = h0;
    ((__half2*)hi)[2 * i + 1] = h1;
}

// ---------------------------------------------------------------------------
// warp-mma helpers (base sm_103 PTX -- tcgen05 is a-gated, unavailable here)
// ---------------------------------------------------------------------------
__device__ __forceinline__ uint32_t smem_u32(const void* p) {
    uint32_t a;
    asm("{ .reg .u64 t; cvta.to.shared.u64 t, %1; cvt.u32.u64 %0, t; }"
        : "=r"(a) : "l"(p));
    return a;
}
#define LDSM_X4(r0, r1, r2, r3, addr)                                        \
    asm volatile("ldmatrix.sync.aligned.m8n8.x4.shared.b16 {%0,%1,%2,%3}, [%4];" \
                 : "=r"(r0), "=r"(r1), "=r"(r2), "=r"(r3) : "r"(addr))
#define LDSM_X4_T(r0, r1, r2, r3, addr)                                      \
    asm volatile("ldmatrix.sync.aligned.m8n8.x4.trans.shared.b16 {%0,%1,%2,%3}, [%4];" \
                 : "=r"(r0), "=r"(r1), "=r"(r2), "=r"(r3) : "r"(addr))
#define MMA16816(d, a, b0, b1)                                               \
    asm volatile("mma.sync.aligned.m16n8k16.row.col.f32.f16.f16.f32 "        \
                 "{%0,%1,%2,%3}, {%4,%5,%6,%7}, {%8,%9}, {%0,%1,%2,%3};"     \
                 : "+f"((d)[0]), "+f"((d)[1]), "+f"((d)[2]), "+f"((d)[3])    \
                 : "r"((a)[0]), "r"((a)[1]), "r"((a)[2]), "r"((a)[3]),       \
                   "r"(b0), "r"(b1))
#define CP_ASYNC16(dst, src)                                                 \
    asm volatile("cp.async.cg.shared.global [%0], [%1], 16;"                 \
                 :: "r"(dst), "l"(src))
#define CP_COMMIT()  asm volatile("cp.async.commit_group;" ::: "memory")
#define CP_WAIT0()   asm volatile("cp.async.wait_group 0;" ::: "memory")
#define CP_WAIT1()   asm volatile("cp.async.wait_group 1;" ::: "memory")

// ---------------------------------------------------------------------------
// C[M,N] = alpha * A[M,768] @ W[N,768]^T + bias, single-product fp16.
// out_half: write fp16 (no bias) instead of fp32.
// 128x128 CTA tile, BK=64, 8 warps (32x64 each), cp.async double-buffered.
// gather!=0: logical A row r -> (r/204)*1576 + g_idx[r%204]
// ---------------------------------------------------------------------------
#define LDS_PAD 72
#define ARR_ELEMS (128 * LDS_PAD)
#define BUF_ELEMS (2 * ARR_ELEMS)          // Ah | Bh
#define GEMM_SMEM (2 * BUF_ELEMS * 2)      // double buffer, bytes

__global__ __launch_bounds__(256)
void gemm_mma(const __half* __restrict__ Ah, const __half* __restrict__ Bh,
              void* __restrict__ Cout, int M, int N,
              const float* __restrict__ bias, float alpha, int gather,
              int out_half)
{
    extern __shared__ __half smem[];
    const int tid = threadIdx.x;
    const int wid = tid >> 5, lane = tid & 31;
    const int bm = blockIdx.y * 128, bn = blockIdx.x * 128;
    const int warp_m = wid & 3, warp_n = wid >> 2;
    const uint32_t sbase = smem_u32(smem);

    float acc[2][8][4];
#pragma unroll
    for (int mt = 0; mt < 2; mt++)
#pragma unroll
        for (int nt = 0; nt < 8; nt++)
#pragma unroll
            for (int e = 0; e < 4; e++) acc[mt][nt][e] = 0.f;

    const int a_row  = lane & 15;
    const int a_koff = (lane >> 4) << 3;
    const int b_row  = ((lane >> 4) << 3) + (lane & 7);
    const int b_koff = ((lane >> 3) & 1) << 3;

    auto stage = [&](int c, int buf) {
        const int k0 = c * 64;
#pragma unroll
        for (int t = 0; t < 8; t++) {
            int i = tid + 256 * t;       // [0,2048)
            int a = i >> 10, row = (i >> 3) & 127, slot = i & 7;
            const __half* src;
            int r;
            if (a == 0) {
                r = bm + row; if (r >= M) r = 0;
                if (gather) { int bb = r / MG; int mm = r - bb * MG; r = bb * NTOK + g_idx[mm]; }
                src = Ah;
            } else {
                r = bn + row;
                src = Bh;
            }
            uint32_t dst = sbase +
                (uint32_t)(buf * BUF_ELEMS + a * ARR_ELEMS + row * LDS_PAD + slot * 8) * 2;
            CP_ASYNC16(dst, src + (size_t)r * CDIM + k0 + slot * 8);
        }
        CP_COMMIT();
    };

    stage(0, 0);

    for (int c = 0; c < 12; c++) {
        const int buf = c & 1;
        CP_WAIT0();
        __syncthreads();
        if (c + 1 < 12) stage(c + 1, buf ^ 1);

        const uint32_t sA  = sbase + (uint32_t)(buf * BUF_ELEMS) * 2;
        const uint32_t sB  = sA + ARR_ELEMS * 2;

#pragma unroll
        for (int ks = 0; ks < 4; ks++) {
            const int kb = ks * 16;
            uint32_t bh[4][4], af[2][4];
#pragma unroll
            for (int g = 0; g < 4; g++) {
                uint32_t off = (uint32_t)((warp_n * 64 + g * 16 + b_row) * LDS_PAD + kb + b_koff) * 2;
                LDSM_X4(bh[g][0], bh[g][1], bh[g][2], bh[g][3], sB + off);
            }
#pragma unroll
            for (int mt = 0; mt < 2; mt++) {
                uint32_t off = (uint32_t)((warp_m * 32 + mt * 16 + a_row) * LDS_PAD + kb + a_koff) * 2;
                LDSM_X4(af[mt][0], af[mt][1], af[mt][2], af[mt][3], sA + off);
            }
#pragma unroll
            for (int mt = 0; mt < 2; mt++)
#pragma unroll
                for (int g = 0; g < 4; g++) {
                    MMA16816(acc[mt][2 * g],     af[mt], bh[g][0], bh[g][1]);
                    MMA16816(acc[mt][2 * g + 1], af[mt], bh[g][2], bh[g][3]);
                }
        }
        __syncthreads();
    }

    // ---- epilogue ----
    const int qrow = lane >> 2, qcol = (lane & 3) * 2;
#pragma unroll
    for (int mt = 0; mt < 2; mt++) {
#pragma unroll
        for (int half = 0; half < 2; half++) {
            int r = bm + warp_m * 32 + mt * 16 + qrow + half * 8;
            if (r >= M) continue;
#pragma unroll
            for (int nt = 0; nt < 8; nt++) {
                int cc = bn + warp_n * 64 + nt * 8 + qcol;
                float ox = acc[mt][nt][2 * half]     * alpha;
                float oy = acc[mt][nt][2 * half + 1] * alpha;
                if (out_half) {
                    __half2 hv;
                    hv.x = __float2half(ox); hv.y = __float2half(oy);
                    *(__half2*)((__half*)Cout + (size_t)r * N + cc) = hv;
                } else {
                    float2 o;
                    o.x = ox + (bias ? bias[cc]     : 0.f);
                    o.y = oy + (bias ? bias[cc + 1] : 0.f);
                    *(float2*)((float*)Cout + (size_t)r * N + cc) = o;
                }
            }
        }
    }
}

// ---------------------------------------------------------------------------
// Tensor-core fused attention. Block = 256 threads (8 warps), one (b, h,
// 128-row q-tile). Warp w owns rows 16w..16w+15 over all 208 key columns
// (204 real + 4 masked pad). Two cp.async groups: (Q,K) then (V); V load
// hides behind QK^T + softmax. P fragments stay in registers for PV.
// ---------------------------------------------------------------------------
#define ALD 72
#define QROWS 128
#define ATTN_SMEM ((QROWS + 208 + 208) * ALD * 2)   // bytes

__global__ __launch_bounds__(256) void attn_mma_kernel() {
    extern __shared__ __half sm16[];
    const int b = blockIdx.z, h = blockIdx.y;
    const int n0 = blockIdx.x * QROWS;
    const int tid = threadIdx.x, w = tid >> 5, lane = tid & 31;
    const uint32_t sb = smem_u32(sm16);
    // layout: Q rows [0,128), K rows [128,336), V rows [336,544), stride ALD

    // ---- group 1: Q (128x64) + K (208x64) ----
#pragma unroll
    for (int t = 0; t < 4; t++) {
        int i = tid + 256 * t;           // [0,1024)
        int r = i >> 3, q = i & 7;
        int n = n0 + r; if (n >= NTOK) n = NTOK - 1;
        const __half* src = g_Q16 + (size_t)(b * NTOK + n) * CDIM + h * HD + q * 8;
        CP_ASYNC16(sb + (uint32_t)(r * ALD + q * 8) * 2, src);
    }
#pragma unroll
    for (int t = 0; t < 7; t++) {
        int i = tid + 256 * t;           // [0,1792) need 1664
        if (i < 1664) {
            int m = i >> 3, q = i & 7;
            int mc = m < MG ? m : MG - 1;
            const __half* base = g_KV16 + (size_t)(b * MG + mc) * (2 * CDIM) + h * HD + q * 8;
            CP_ASYNC16(sb + (uint32_t)((QROWS + m) * ALD + q * 8) * 2, base);
        }
    }
    CP_COMMIT();
    // ---- group 2: V (208x64) ----
#pragma unroll
    for (int t = 0; t < 7; t++) {
        int i = tid + 256 * t;
        if (i < 1664) {
            int m = i >> 3, q = i & 7;
            int mc = m < MG ? m : MG - 1;
            const __half* base = g_KV16 + (size_t)(b * MG + mc) * (2 * CDIM) + h * HD + CDIM + q * 8;
            CP_ASYNC16(sb + (uint32_t)((QROWS + 208 + m) * ALD + q * 8) * 2, base);
        }
    }
    CP_COMMIT();

    CP_WAIT1();                 // Q + K ready
    __syncthreads();

    const int a_row  = lane & 15;
    const int a_koff = (lane >> 4) << 3;
    const int b_row  = ((lane >> 4) << 3) + (lane & 7);
    const int b_koff = ((lane >> 3) & 1) << 3;

    // ---- QK^T: s[26 tiles][4] ----
    float s[26][4];
#pragma unroll
    for (int nt = 0; nt < 26; nt++)
#pragma unroll
        for (int e = 0; e < 4; e++) s[nt][e] = 0.f;

#pragma unroll
    for (int ks = 0; ks < 4; ks++) {
        const int kb = ks * 16;
        uint32_t af[4];
        LDSM_X4(af[0], af[1], af[2], af[3],
                sb + (uint32_t)((w * 16 + a_row) * ALD + kb + a_koff) * 2);
#pragma unroll
        for (int g = 0; g < 13; g++) {
            uint32_t b0, b1, b2, b3;
            LDSM_X4(b0, b1, b2, b3,
                    sb + (uint32_t)((QROWS + g * 16 + b_row) * ALD + kb + b_koff) * 2);
            MMA16816(s[2 * g],     af, b0, b1);
            MMA16816(s[2 * g + 1], af, b2, b3);
        }
    }

    // ---- mask + softmax (rows qrow, qrow+8) ----
    const int qrow = lane >> 2;
    const int nrow0 = n0 + w * 16 + qrow;
    const int nrow1 = nrow0 + 8;
    const int nf0 = (nrow0 < NTOK) ? nrow0 / NO : 0;
    const int nf1 = (nrow1 < NTOK) ? nrow1 / NO : 0;

    float mx0 = -1e30f, mx1 = -1e30f;
#pragma unroll
    for (int nt = 0; nt < 26; nt++) {
#pragma unroll
        for (int e = 0; e < 2; e++) {
            int c = nt * 8 + (lane & 3) * 2 + e;
            if (c >= MG) { s[nt][e] = -1e30f; s[nt][2 + e] = -1e30f; continue; }
            if (c >= NFR) {
                int mm = c - NFR;
                int f = (mm < 100) ? mm / 25 : 4 + (mm - 100) / 24;
                if (f != nf0) s[nt][e]     *= 0.8f;
                if (f != nf1) s[nt][2 + e] *= 0.8f;
            }
            mx0 = fmaxf(mx0, s[nt][e]);
            mx1 = fmaxf(mx1, s[nt][2 + e]);
        }
    }
    mx0 = fmaxf(mx0, __shfl_xor_sync(0xffffffffu, mx0, 1));
    mx0 = fmaxf(mx0, __shfl_xor_sync(0xffffffffu, mx0, 2));
    mx1 = fmaxf(mx1, __shfl_xor_sync(0xffffffffu, mx1, 1));
    mx1 = fmaxf(mx1, __shfl_xor_sync(0xffffffffu, mx1, 2));

    float sum0 = 0.f, sum1 = 0.f;
    uint32_t p2[26][2];
#pragma unroll
    for (int nt = 0; nt < 26; nt++) {
        float e0 = __expf(s[nt][0] - mx0);
        float e1 = __expf(s[nt][1] - mx0);
        float e2 = __expf(s[nt][2] - mx1);
        float e3 = __expf(s[nt][3] - mx1);
        sum0 += e0 + e1; sum1 += e2 + e3;
        __half2 lo, hi;
        lo.x = __float2half(e0); lo.y = __float2half(e1);
        hi.x = __float2half(e2); hi.y = __float2half(e3);
        p2[nt][0] = *(uint32_t*)&lo;
        p2[nt][1] = *(uint32_t*)&hi;
    }
    sum0 += __shfl_xor_sync(0xffffffffu, sum0, 1);
    sum0 += __shfl_xor_sync(0xffffffffu, sum0, 2);
    sum1 += __shfl_xor_sync(0xffffffffu, sum1, 1);
    sum1 += __shfl_xor_sync(0xffffffffu, sum1, 2);
    const float inv0 = 1.f / sum0, inv1 = 1.f / sum1;

    CP_WAIT0();                 // V ready
    __syncthreads();

    // ---- PV: out[16 x 64] += P[16 x 208] * V[208 x 64] ----
    float o[8][4];
#pragma unroll
    for (int nt = 0; nt < 8; nt++)
#pragma unroll
        for (int e = 0; e < 4; e++) o[nt][e] = 0.f;

#pragma unroll
    for (int ng = 0; ng < 4; ng++) {
#pragma unroll
        for (int kk = 0; kk < 13; kk++) {
            uint32_t v0, v1, v2, v3;
            LDSM_X4_T(v0, v1, v2, v3,
                      sb + (uint32_t)((QROWS + 208 + kk * 16 + (lane & 15)) * ALD
                                      + ng * 16 + ((lane >> 4) << 3)) * 2);
            uint32_t af[4] = { p2[2 * kk][0], p2[2 * kk][1],
                               p2[2 * kk + 1][0], p2[2 * kk + 1][1] };
            MMA16816(o[2 * ng],     af, v0, v1);
            MMA16816(o[2 * ng + 1], af, v2, v3);
        }
    }

    // ---- epilogue: normalize + fp16 store ----
    if (nrow0 < NTOK) {
        __half* dst = g_AOh + (size_t)(b * NTOK + nrow0) * CDIM + h * HD;
#pragma unroll
        for (int nt = 0; nt < 8; nt++) {
            int d = nt * 8 + (lane & 3) * 2;
            __half2 hv;
            hv.x = __float2half(o[nt][0] * inv0);
            hv.y = __float2half(o[nt][1] * inv0);
            *(__half2*)(dst + d) = hv;
        }
    }
    if (nrow1 < NTOK) {
        __half* dst = g_AOh + (size_t)(b * NTOK + nrow1) * CDIM + h * HD;
#pragma unroll
        for (int nt = 0; nt < 8; nt++) {
            int d = nt * 8 + (lane & 3) * 2;
            __half2 hv;
            hv.x = __float2half(o[nt][2] * inv1);
            hv.y = __float2half(o[nt][3] * inv1);
            *(__half2*)(dst + d) = hv;
        }
    }
}

// ---------------------------------------------------------------------------
extern "C" void kernel_launch(void* const* d_in, const int* in_sizes, int n_in,
                              void* d_out, int out_size) {
    const float* x      = (const float*)d_in[0];
    const float* qkv_w  = (const float*)d_in[1];
    const float* proj_w = (const float*)d_in[2];
    const float* proj_b = (const float*)d_in[3];
    float* out = (float*)d_out;

    __half *pXh, *pWh, *pPh, *pAOh, *pQ16, *pKV16;
    cudaGetSymbolAddress((void**)&pXh, g_Xh);
    cudaGetSymbolAddress((void**)&pWh, g_Wh);
    cudaGetSymbolAddress((void**)&pPh, g_Ph);
    cudaGetSymbolAddress((void**)&pAOh, g_AOh);
    cudaGetSymbolAddress((void**)&pQ16, g_Q16);
    cudaGetSymbolAddress((void**)&pKV16, g_KV16);

    cudaFuncSetAttribute(gemm_mma, cudaFuncAttributeMaxDynamicSharedMemorySize, GEMM_SMEM);
    cudaFuncSetAttribute(attn_mma_kernel, cudaFuncAttributeMaxDynamicSharedMemorySize,
                         ATTN_SMEM);

    init_idx_kernel<<<1, 256>>>();

    int n4x = ROWS_X * CDIM / 4;
    int n4w = 3 * CDIM * CDIM / 4;
    int n4p = CDIM * CDIM / 4;
    cvt_hi_kernel<<<(n4x + 255) / 256, 256>>>(x, pXh, n4x);
    cvt_hi_kernel<<<(n4w + 255) / 256, 256>>>(qkv_w, pWh, n4w);
    cvt_hi_kernel<<<(n4p + 255) / 256, 256>>>(proj_w, pPh, n4p);

    // Q16 = fp16( X @ Wq^T * 0.125 )
    dim3 gq(CDIM / 128, (ROWS_X + 127) / 128);
    gemm_mma<<<gq, 256, GEMM_SMEM>>>(pXh, pWh, pQ16,
                                     ROWS_X, CDIM, nullptr, 0.125f, 0, 1);
    // KV16 = fp16( gathered X @ [Wk|Wv]^T )   (1632 x 1536)
    dim3 gkv(1536 / 128, (ROWS_KV + 127) / 128);
    gemm_mma<<<gkv, 256, GEMM_SMEM>>>(pXh, pWh + CDIM * CDIM, pKV16,
                                      ROWS_KV, 2 * CDIM, nullptr, 1.f, 1, 1);
    // fused tensor-core attention -> fp16 AO
    dim3 ga((NTOK + QROWS - 1) / QROWS, NH, NB);
    attn_mma_kernel<<<ga, 256, ATTN_SMEM>>>();

    // out = AO @ proj_w^T + proj_b  (fp32)
    gemm_mma<<<gq, 256, GEMM_SMEM>>>(pAOh, pPh, out,
                                     ROWS_X, CDIM, proj_b, 1.f, 0, 0);
}

// round 10
// speedup vs baseline: 8.5661x; 1.1456x over previous
#include <cuda_runtime.h>
#include <cuda_fp16.h>
#include <cstdint>

#define NFR 8
#define NO 197
#define NB 8
#define NTOK 1576          // 8*197
#define CDIM 768
#define NH 12
#define HD 64
#define MG 204             // gathered tokens
#define ROWS_X 12608       // 64*197
#define ROWS_KV 1632       // 8*204

// ---------------- scratch (no allocs allowed -> device globals) -------------
__device__ int    g_idx[MG];
__device__ __half g_Xh[ROWS_X * CDIM];
__device__ __half g_Wh[3 * CDIM * CDIM];
__device__ __half g_Ph[CDIM * CDIM];
__device__ __half g_Q16[ROWS_X * CDIM];        // Q projection (x0.125), fp16
__device__ __half g_KV16[ROWS_KV * 2 * CDIM];  // [K(768) | V(768)] fp16
__device__ __half g_AOh[ROWS_X * CDIM];

// ---------------------------------------------------------------------------
// One launch: build gather indices + convert x, qkv_w, proj_w to fp16.
// ---------------------------------------------------------------------------
#define N4X (ROWS_X * CDIM / 4)
#define N4W (3 * CDIM * CDIM / 4)
#define N4P (CDIM * CDIM / 4)
#define N4ALL (N4X + N4W + N4P)

__global__ void prep_kernel(const float* __restrict__ x,
                            const float* __restrict__ qkv_w,
                            const float* __restrict__ proj_w) {
    int i = blockIdx.x * blockDim.x + threadIdx.x;
    if (i < MG) {
        int m = i;
        if (m < NFR) g_idx[m] = m * NO;
        else {
            int mm = m - NFR;
            int f, j;
            if (mm < 100) { f = mm / 25; j = mm - f * 25; }
            else          { f = 4 + (mm - 100) / 24; j = (mm - 100) - (f - 4) * 24; }
            g_idx[m] = f * NO + 1 + f + 8 * j;
        }
    }
    if (i >= N4ALL) return;
    const float* src; __half* dst; int k;
    if (i < N4X)            { src = x;      dst = g_Xh; k = i; }
    else if (i < N4X + N4W) { src = qkv_w;  dst = g_Wh; k = i - N4X; }
    else                    { src = proj_w; dst = g_Ph; k = i - N4X - N4W; }
    float4 v = ((const float4*)src)[k];
    __half2 h0, h1;
    h0.x = __float2half(v.x); h0.y = __float2half(v.y);
    h1.x = __float2half(v.z); h1.y = __float2half(v.w);
    ((__half2*)dst)[2 * k]     = h0;
    ((__half2*)dst)[2 * k + 1] = h1;
}

// ---------------------------------------------------------------------------
// warp-mma helpers (base sm_103 PTX -- tcgen05 is a-gated, unavailable here)
// ---------------------------------------------------------------------------
__device__ __forceinline__ uint32_t smem_u32(const void* p) {
    uint32_t a;
    asm("{ .reg .u64 t; cvta.to.shared.u64 t, %1; cvt.u32.u64 %0, t; }"
        : "=r"(a) : "l"(p));
    return a;
}
#define LDSM_X4(r0, r1, r2, r3, addr)                                        \
    asm volatile("ldmatrix.sync.aligned.m8n8.x4.shared.b16 {%0,%1,%2,%3}, [%4];" \
                 : "=r"(r0), "=r"(r1), "=r"(r2), "=r"(r3) : "r"(addr))
#define LDSM_X4_T(r0, r1, r2, r3, addr)                                      \
    asm volatile("ldmatrix.sync.aligned.m8n8.x4.trans.shared.b16 {%0,%1,%2,%3}, [%4];" \
                 : "=r"(r0), "=r"(r1), "=r"(r2), "=r"(r3) : "r"(addr))
#define MMA16816(d, a, b0, b1)                                               \
    asm volatile("mma.sync.aligned.m16n8k16.row.col.f32.f16.f16.f32 "        \
                 "{%0,%1,%2,%3}, {%4,%5,%6,%7}, {%8,%9}, {%0,%1,%2,%3};"     \
                 : "+f"((d)[0]), "+f"((d)[1]), "+f"((d)[2]), "+f"((d)[3])    \
                 : "r"((a)[0]), "r"((a)[1]), "r"((a)[2]), "r"((a)[3]),       \
                   "r"(b0), "r"(b1))
#define CP_ASYNC16(dst, src)                                                 \
    asm volatile("cp.async.cg.shared.global [%0], [%1], 16;"                 \
                 :: "r"(dst), "l"(src))
#define CP_COMMIT()  asm volatile("cp.async.commit_group;" ::: "memory")
#define CP_WAIT0()   asm volatile("cp.async.wait_group 0;" ::: "memory")
#define CP_WAIT1()   asm volatile("cp.async.wait_group 1;" ::: "memory")

// ---------------------------------------------------------------------------
// GEMM body: C[128x128 tile @ (bm,bn)] = alpha * A @ B^T (+bias).
// Single-product fp16, BK=64, 8 warps, cp.async double-buffered.
// ---------------------------------------------------------------------------
#define LDS_PAD 72
#define ARR_ELEMS (128 * LDS_PAD)
#define BUF_ELEMS (2 * ARR_ELEMS)          // Ah | Bh
#define GEMM_SMEM (2 * BUF_ELEMS * 2)      // double buffer, bytes

__device__ __forceinline__
void gemm_body(const __half* __restrict__ Ah, const __half* __restrict__ Bh,
               void* __restrict__ Cout, int M, int N,
               const float* __restrict__ bias, float alpha, int gather,
               int out_half, int bm, int bn, __half* smem)
{
    const int tid = threadIdx.x;
    const int wid = tid >> 5, lane = tid & 31;
    const int warp_m = wid & 3, warp_n = wid >> 2;
    const uint32_t sbase = smem_u32(smem);

    float acc[2][8][4];
#pragma unroll
    for (int mt = 0; mt < 2; mt++)
#pragma unroll
        for (int nt = 0; nt < 8; nt++)
#pragma unroll
            for (int e = 0; e < 4; e++) acc[mt][nt][e] = 0.f;

    const int a_row  = lane & 15;
    const int a_koff = (lane >> 4) << 3;
    const int b_row  = ((lane >> 4) << 3) + (lane & 7);
    const int b_koff = ((lane >> 3) & 1) << 3;

    auto stage = [&](int c, int buf) {
        const int k0 = c * 64;
#pragma unroll
        for (int t = 0; t < 8; t++) {
            int i = tid + 256 * t;       // [0,2048)
            int a = i >> 10, row = (i >> 3) & 127, slot = i & 7;
            const __half* src;
            int r;
            if (a == 0) {
                r = bm + row; if (r >= M) r = 0;
                if (gather) { int bb = r / MG; int mm = r - bb * MG; r = bb * NTOK + g_idx[mm]; }
                src = Ah;
            } else {
                r = bn + row;
                src = Bh;
            }
            uint32_t dst = sbase +
                (uint32_t)(buf * BUF_ELEMS + a * ARR_ELEMS + row * LDS_PAD + slot * 8) * 2;
            CP_ASYNC16(dst, src + (size_t)r * CDIM + k0 + slot * 8);
        }
        CP_COMMIT();
    };

    stage(0, 0);

    for (int c = 0; c < 12; c++) {
        const int buf = c & 1;
        CP_WAIT0();
        __syncthreads();
        if (c + 1 < 12) stage(c + 1, buf ^ 1);

        const uint32_t sA = sbase + (uint32_t)(buf * BUF_ELEMS) * 2;
        const uint32_t sB = sA + ARR_ELEMS * 2;

#pragma unroll
        for (int ks = 0; ks < 4; ks++) {
            const int kb = ks * 16;
            uint32_t bh[4][4], af[2][4];
#pragma unroll
            for (int g = 0; g < 4; g++) {
                uint32_t off = (uint32_t)((warp_n * 64 + g * 16 + b_row) * LDS_PAD + kb + b_koff) * 2;
                LDSM_X4(bh[g][0], bh[g][1], bh[g][2], bh[g][3], sB + off);
            }
#pragma unroll
            for (int mt = 0; mt < 2; mt++) {
                uint32_t off = (uint32_t)((warp_m * 32 + mt * 16 + a_row) * LDS_PAD + kb + a_koff) * 2;
                LDSM_X4(af[mt][0], af[mt][1], af[mt][2], af[mt][3], sA + off);
            }
#pragma unroll
            for (int mt = 0; mt < 2; mt++)
#pragma unroll
                for (int g = 0; g < 4; g++) {
                    MMA16816(acc[mt][2 * g],     af[mt], bh[g][0], bh[g][1]);
                    MMA16816(acc[mt][2 * g + 1], af[mt], bh[g][2], bh[g][3]);
                }
        }
        __syncthreads();
    }

    const int qrow = lane >> 2, qcol = (lane & 3) * 2;
#pragma unroll
    for (int mt = 0; mt < 2; mt++) {
#pragma unroll
        for (int half = 0; half < 2; half++) {
            int r = bm + warp_m * 32 + mt * 16 + qrow + half * 8;
            if (r >= M) continue;
#pragma unroll
            for (int nt = 0; nt < 8; nt++) {
                int cc = bn + warp_n * 64 + nt * 8 + qcol;
                float ox = acc[mt][nt][2 * half]     * alpha;
                float oy = acc[mt][nt][2 * half + 1] * alpha;
                if (out_half) {
                    __half2 hv;
                    hv.x = __float2half(ox); hv.y = __float2half(oy);
                    *(__half2*)((__half*)Cout + (size_t)r * N + cc) = hv;
                } else {
                    float2 o;
                    o.x = ox + (bias ? bias[cc]     : 0.f);
                    o.y = oy + (bias ? bias[cc + 1] : 0.f);
                    *(float2*)((float*)Cout + (size_t)r * N + cc) = o;
                }
            }
        }
    }
}

// ---- merged Q + KV projection (750 linearized CTAs) ----
#define QTILES_M 99            // ceil(12608/128)
#define QBLOCKS (QTILES_M * 6) // 594
#define KVTILES_M 13           // ceil(1632/128)
#define KVBLOCKS (KVTILES_M * 12)

__global__ __launch_bounds__(256, 2)
void gemm_qkv_kernel() {
    extern __shared__ __half smem[];
    int bid = blockIdx.x;
    if (bid < QBLOCKS) {
        int bm = (bid / 6) * 128, bn = (bid % 6) * 128;
        gemm_body(g_Xh, g_Wh, g_Q16, ROWS_X, CDIM,
                  nullptr, 0.125f, 0, 1, bm, bn, smem);
    } else {
        bid -= QBLOCKS;
        int bm = (bid % KVTILES_M) * 128, bn = (bid / KVTILES_M) * 128;
        gemm_body(g_Xh, g_Wh + CDIM * CDIM, g_KV16, ROWS_KV, 2 * CDIM,
                  nullptr, 1.f, 1, 1, bm, bn, smem);
    }
}

// ---- output projection ----
__global__ __launch_bounds__(256, 2)
void gemm_proj_kernel(float* __restrict__ out, const float* __restrict__ bias) {
    extern __shared__ __half smem[];
    int bid = blockIdx.x;
    int bm = (bid / 6) * 128, bn = (bid % 6) * 128;
    gemm_body(g_AOh, g_Ph, out, ROWS_X, CDIM, bias, 1.f, 0, 0, bm, bn, smem);
}

// ---------------------------------------------------------------------------
// Tensor-core fused attention. Block = 256 threads (8 warps), one (b, h,
// 128-row q-tile). Warp w owns rows 16w..16w+15 over 208 key columns
// (204 real + 4 masked pad). Two cp.async groups: (Q,K) then (V).
// ---------------------------------------------------------------------------
#define ALD 72
#define QROWS 128
#define ATTN_SMEM ((QROWS + 208 + 208) * ALD * 2)   // bytes

__global__ __launch_bounds__(256) void attn_mma_kernel() {
    extern __shared__ __half sm16[];
    const int b = blockIdx.z, h = blockIdx.y;
    const int n0 = blockIdx.x * QROWS;
    const int tid = threadIdx.x, w = tid >> 5, lane = tid & 31;
    const uint32_t sb = smem_u32(sm16);

    // ---- group 1: Q (128x64) + K (208x64) ----
#pragma unroll
    for (int t = 0; t < 4; t++) {
        int i = tid + 256 * t;
        int r = i >> 3, q = i & 7;
        int n = n0 + r; if (n >= NTOK) n = NTOK - 1;
        const __half* src = g_Q16 + (size_t)(b * NTOK + n) * CDIM + h * HD + q * 8;
        CP_ASYNC16(sb + (uint32_t)(r * ALD + q * 8) * 2, src);
    }
#pragma unroll
    for (int t = 0; t < 7; t++) {
        int i = tid + 256 * t;
        if (i < 1664) {
            int m = i >> 3, q = i & 7;
            int mc = m < MG ? m : MG - 1;
            const __half* base = g_KV16 + (size_t)(b * MG + mc) * (2 * CDIM) + h * HD + q * 8;
            CP_ASYNC16(sb + (uint32_t)((QROWS + m) * ALD + q * 8) * 2, base);
        }
    }
    CP_COMMIT();
    // ---- group 2: V (208x64) ----
#pragma unroll
    for (int t = 0; t < 7; t++) {
        int i = tid + 256 * t;
        if (i < 1664) {
            int m = i >> 3, q = i & 7;
            int mc = m < MG ? m : MG - 1;
            const __half* base = g_KV16 + (size_t)(b * MG + mc) * (2 * CDIM) + h * HD + CDIM + q * 8;
            CP_ASYNC16(sb + (uint32_t)((QROWS + 208 + m) * ALD + q * 8) * 2, base);
        }
    }
    CP_COMMIT();

    CP_WAIT1();                 // Q + K ready
    __syncthreads();

    const int a_row  = lane & 15;
    const int a_koff = (lane >> 4) << 3;
    const int b_row  = ((lane >> 4) << 3) + (lane & 7);
    const int b_koff = ((lane >> 3) & 1) << 3;

    float s[26][4];
#pragma unroll
    for (int nt = 0; nt < 26; nt++)
#pragma unroll
        for (int e = 0; e < 4; e++) s[nt][e] = 0.f;

#pragma unroll
    for (int ks = 0; ks < 4; ks++) {
        const int kb = ks * 16;
        uint32_t af[4];
        LDSM_X4(af[0], af[1], af[2], af[3],
                sb + (uint32_t)((w * 16 + a_row) * ALD + kb + a_koff) * 2);
#pragma unroll
        for (int g = 0; g < 13; g++) {
            uint32_t b0, b1, b2, b3;
            LDSM_X4(b0, b1, b2, b3,
                    sb + (uint32_t)((QROWS + g * 16 + b_row) * ALD + kb + b_koff) * 2);
            MMA16816(s[2 * g],     af, b0, b1);
            MMA16816(s[2 * g + 1], af, b2, b3);
        }
    }

    const int qrow = lane >> 2;
    const int nrow0 = n0 + w * 16 + qrow;
    const int nrow1 = nrow0 + 8;
    const int nf0 = (nrow0 < NTOK) ? nrow0 / NO : 0;
    const int nf1 = (nrow1 < NTOK) ? nrow1 / NO : 0;

    float mx0 = -1e30f, mx1 = -1e30f;
#pragma unroll
    for (int nt = 0; nt < 26; nt++) {
#pragma unroll
        for (int e = 0; e < 2; e++) {
            int c = nt * 8 + (lane & 3) * 2 + e;
            if (c >= MG) { s[nt][e] = -1e30f; s[nt][2 + e] = -1e30f; continue; }
            if (c >= NFR) {
                int mm = c - NFR;
                int f = (mm < 100) ? mm / 25 : 4 + (mm - 100) / 24;
                if (f != nf0) s[nt][e]     *= 0.8f;
                if (f != nf1) s[nt][2 + e] *= 0.8f;
            }
            mx0 = fmaxf(mx0, s[nt][e]);
            mx1 = fmaxf(mx1, s[nt][2 + e]);
        }
    }
    mx0 = fmaxf(mx0, __shfl_xor_sync(0xffffffffu, mx0, 1));
    mx0 = fmaxf(mx0, __shfl_xor_sync(0xffffffffu, mx0, 2));
    mx1 = fmaxf(mx1, __shfl_xor_sync(0xffffffffu, mx1, 1));
    mx1 = fmaxf(mx1, __shfl_xor_sync(0xffffffffu, mx1, 2));

    float sum0 = 0.f, sum1 = 0.f;
    uint32_t p2[26][2];
#pragma unroll
    for (int nt = 0; nt < 26; nt++) {
        float e0 = __expf(s[nt][0] - mx0);
        float e1 = __expf(s[nt][1] - mx0);
        float e2 = __expf(s[nt][2] - mx1);
        float e3 = __expf(s[nt][3] - mx1);
        sum0 += e0 + e1; sum1 += e2 + e3;
        __half2 lo, hi;
        lo.x = __float2half(e0); lo.y = __float2half(e1);
        hi.x = __float2half(e2); hi.y = __float2half(e3);
        p2[nt][0] = *(uint32_t*)&lo;
        p2[nt][1] = *(uint32_t*)&hi;
    }
    sum0 += __shfl_xor_sync(0xffffffffu, sum0, 1);
    sum0 += __shfl_xor_sync(0xffffffffu, sum0, 2);
    sum1 += __shfl_xor_sync(0xffffffffu, sum1, 1);
    sum1 += __shfl_xor_sync(0xffffffffu, sum1, 2);
    const float inv0 = 1.f / sum0, inv1 = 1.f / sum1;

    CP_WAIT0();                 // V ready
    __syncthreads();

    float o[8][4];
#pragma unroll
    for (int nt = 0; nt < 8; nt++)
#pragma unroll
        for (int e = 0; e < 4; e++) o[nt][e] = 0.f;

#pragma unroll
    for (int ng = 0; ng < 4; ng++) {
#pragma unroll
        for (int kk = 0; kk < 13; kk++) {
            uint32_t v0, v1, v2, v3;
            LDSM_X4_T(v0, v1, v2, v3,
                      sb + (uint32_t)((QROWS + 208 + kk * 16 + (lane & 15)) * ALD
                                      + ng * 16 + ((lane >> 4) << 3)) * 2);
            uint32_t af[4] = { p2[2 * kk][0], p2[2 * kk][1],
                               p2[2 * kk + 1][0], p2[2 * kk + 1][1] };
            MMA16816(o[2 * ng],     af, v0, v1);
            MMA16816(o[2 * ng + 1], af, v2, v3);
        }
    }

    if (nrow0 < NTOK) {
        __half* dst = g_AOh + (size_t)(b * NTOK + nrow0) * CDIM + h * HD;
#pragma unroll
        for (int nt = 0; nt < 8; nt++) {
            int d = nt * 8 + (lane & 3) * 2;
            __half2 hv;
            hv.x = __float2half(o[nt][0] * inv0);
            hv.y = __float2half(o[nt][1] * inv0);
            *(__half2*)(dst + d) = hv;
        }
    }
    if (nrow1 < NTOK) {
        __half* dst = g_AOh + (size_t)(b * NTOK + nrow1) * CDIM + h * HD;
#pragma unroll
        for (int nt = 0; nt < 8; nt++) {
            int d = nt * 8 + (lane & 3) * 2;
            __half2 hv;
            hv.x = __float2half(o[nt][2] * inv1);
            hv.y = __float2half(o[nt][3] * inv1);
            *(__half2*)(dst + d) = hv;
        }
    }
}

// ---------------------------------------------------------------------------
extern "C" void kernel_launch(void* const* d_in, const int* in_sizes, int n_in,
                              void* d_out, int out_size) {
    const float* x      = (const float*)d_in[0];
    const float* qkv_w  = (const float*)d_in[1];
    const float* proj_w = (const float*)d_in[2];
    const float* proj_b = (const float*)d_in[3];
    float* out = (float*)d_out;

    cudaFuncSetAttribute(gemm_qkv_kernel, cudaFuncAttributeMaxDynamicSharedMemorySize, GEMM_SMEM);
    cudaFuncSetAttribute(gemm_proj_kernel, cudaFuncAttributeMaxDynamicSharedMemorySize, GEMM_SMEM);
    cudaFuncSetAttribute(attn_mma_kernel, cudaFuncAttributeMaxDynamicSharedMemorySize, ATTN_SMEM);

    // prep: gather indices + all fp16 conversions
    prep_kernel<<<(N4ALL + 255) / 256, 256>>>(x, qkv_w, proj_w);

    // merged Q + KV projections
    gemm_qkv_kernel<<<QBLOCKS + KVBLOCKS, 256, GEMM_SMEM>>>();

    // fused tensor-core attention -> fp16 AO
    dim3 ga((NTOK + QROWS - 1) / QROWS, NH, NB);
    attn_mma_kernel<<<ga, 256, ATTN_SMEM>>>();

    // out = AO @ proj_w^T + proj_b  (fp32)
    gemm_proj_kernel<<<QBLOCKS, 256, GEMM_SMEM>>>(out, proj_b);
}